// round 1
// baseline (speedup 1.0000x reference)
#include <cuda_runtime.h>
#include <math.h>

// Problem constants
#define Bq 4
#define Sq 4096
#define Dq 1024
#define Mq (Bq * Sq)          // 16384 rows
#define CHUNKq 64
#define NCHUNK (Sq / CHUNKq)  // 64

// ---------------------------------------------------------------------------
// Scratch buffers (device globals — allocation-free per harness rules)
// ---------------------------------------------------------------------------
__device__ float g_buf0[(size_t)Mq * Dq];
__device__ float g_buf1[(size_t)Mq * Dq];
__device__ float g_buf2[(size_t)Mq * Dq];
__device__ float g_buf3[(size_t)Mq * Dq];

// ---------------------------------------------------------------------------
// SGEMM (NT): C[m,n] = sum_k A[m,k] * W[n,k] + bias[n] (+ resid[m,n])
// A: M x K row-major, W: N x K row-major. M,N,K multiples of 128/128/8.
// Tile: 128x128x8, 256 threads, 8x8 per thread.
// ---------------------------------------------------------------------------
template <bool RESID>
__global__ __launch_bounds__(256, 2)
void sgemm_nt_kernel(const float* __restrict__ A, const float* __restrict__ W,
                     const float* __restrict__ bias, const float* __restrict__ resid,
                     float* __restrict__ C, int M, int N, int K)
{
    constexpr int BM = 128, BN = 128, BK = 8, TM = 8, TN = 8;
    __shared__ float As[BK][BM];
    __shared__ float Bs[BK][BN];

    const int tid  = threadIdx.x;
    const int bm   = blockIdx.y * BM;
    const int bn   = blockIdx.x * BN;
    const int lrow = tid >> 1;           // 0..127
    const int lcol = (tid & 1) << 2;     // 0 or 4
    const int trow = (tid >> 4) << 3;    // 0..120 step 8
    const int tcol = (tid & 15) << 3;    // 0..120 step 8

    const float* Ag = A + (size_t)(bm + lrow) * K + lcol;
    const float* Wg = W + (size_t)(bn + lrow) * K + lcol;

    float acc[TM][TN];
#pragma unroll
    for (int i = 0; i < TM; i++)
#pragma unroll
        for (int j = 0; j < TN; j++) acc[i][j] = 0.0f;

    for (int k0 = 0; k0 < K; k0 += BK) {
        float4 a4 = *(const float4*)(Ag + k0);
        float4 w4 = *(const float4*)(Wg + k0);
        As[lcol + 0][lrow] = a4.x;
        As[lcol + 1][lrow] = a4.y;
        As[lcol + 2][lrow] = a4.z;
        As[lcol + 3][lrow] = a4.w;
        Bs[lcol + 0][lrow] = w4.x;
        Bs[lcol + 1][lrow] = w4.y;
        Bs[lcol + 2][lrow] = w4.z;
        Bs[lcol + 3][lrow] = w4.w;
        __syncthreads();

#pragma unroll
        for (int kk = 0; kk < BK; kk++) {
            float ra[TM], rb[TN];
            *(float4*)&ra[0] = *(const float4*)&As[kk][trow];
            *(float4*)&ra[4] = *(const float4*)&As[kk][trow + 4];
            *(float4*)&rb[0] = *(const float4*)&Bs[kk][tcol];
            *(float4*)&rb[4] = *(const float4*)&Bs[kk][tcol + 4];
#pragma unroll
            for (int i = 0; i < TM; i++)
#pragma unroll
                for (int j = 0; j < TN; j++)
                    acc[i][j] = fmaf(ra[i], rb[j], acc[i][j]);
        }
        __syncthreads();
    }

    // Epilogue: bias (+ residual), vectorized stores
#pragma unroll
    for (int i = 0; i < TM; i++) {
        const int m = bm + trow + i;
#pragma unroll
        for (int j = 0; j < TN; j += 4) {
            const int n = bn + tcol + j;
            float4 r;
            r.x = acc[i][j + 0] + bias[n + 0];
            r.y = acc[i][j + 1] + bias[n + 1];
            r.z = acc[i][j + 2] + bias[n + 2];
            r.w = acc[i][j + 3] + bias[n + 3];
            if (RESID) {
                float4 x4 = *(const float4*)&resid[(size_t)m * N + n];
                r.x += x4.x; r.y += x4.y; r.z += x4.z; r.w += x4.w;
            }
            *(float4*)&C[(size_t)m * N + n] = r;
        }
    }
}

// ---------------------------------------------------------------------------
// Phasor kernel: per (b, chunk, d) chain of CHUNK=64 sequence steps.
//   key_phase  = tanh(kp_lin) * ps[d]
//   query_phase= tanh(qp_lin) * ps[d]
//   mr += v*cos(kp); mi += v*sin(kp)              (inclusive cumsum)
//   retrieved = (mr*cos(qp) + mi*sin(qp)) / 32
// Threads indexed so d is fastest -> fully coalesced loads/stores.
// ---------------------------------------------------------------------------
__global__ void phasor_kernel(const float* __restrict__ kp_lin,
                              const float* __restrict__ qp_lin,
                              const float* __restrict__ val,
                              const float* __restrict__ phase_scale,
                              float* __restrict__ retrieved)
{
    const int idx = blockIdx.x * blockDim.x + threadIdx.x; // 262144 chains
    const int d     = idx & (Dq - 1);
    const int chunk = (idx >> 10) & (NCHUNK - 1);
    const int b     = idx >> 16;
    const float ps  = phase_scale[d];
    size_t off = ((size_t)b * Sq + (size_t)chunk * CHUNKq) * Dq + d;

    float mr = 0.0f, mi = 0.0f;
#pragma unroll 4
    for (int s = 0; s < CHUNKq; s++) {
        const float kp = tanhf(kp_lin[off]) * ps;
        const float qp = tanhf(qp_lin[off]) * ps;
        const float v  = val[off];
        float skp, ckp, sqp, cqp;
        sincosf(kp, &skp, &ckp);
        sincosf(qp, &sqp, &cqp);
        mr = fmaf(v, ckp, mr);
        mi = fmaf(v, skp, mi);
        retrieved[off] = (mr * cqp + mi * sqp) * 0.03125f; // 1/sqrt(1024)
        off += Dq;
    }
}

// ---------------------------------------------------------------------------
// LayerNorm over last dim (1024). One block (256 threads) per row.
// ---------------------------------------------------------------------------
__global__ __launch_bounds__(256)
void layernorm_kernel(const float* __restrict__ in,
                      const float* __restrict__ g,
                      const float* __restrict__ b,
                      float* __restrict__ out)
{
    __shared__ float s_sum[8];
    __shared__ float s_sq[8];
    const int row = blockIdx.x;
    const int tid = threadIdx.x;
    const float* rin = in + (size_t)row * Dq;

    float4 x4 = *(const float4*)&rin[tid * 4];
    float s  = x4.x + x4.y + x4.z + x4.w;
    float sq = x4.x * x4.x + x4.y * x4.y + x4.z * x4.z + x4.w * x4.w;

#pragma unroll
    for (int o = 16; o > 0; o >>= 1) {
        s  += __shfl_xor_sync(0xFFFFFFFFu, s, o);
        sq += __shfl_xor_sync(0xFFFFFFFFu, sq, o);
    }
    const int warp = tid >> 5;
    if ((tid & 31) == 0) { s_sum[warp] = s; s_sq[warp] = sq; }
    __syncthreads();
    if (warp == 0) {
        s  = s_sum[tid & 7];
        sq = s_sq[tid & 7];
#pragma unroll
        for (int o = 4; o > 0; o >>= 1) {
            s  += __shfl_xor_sync(0xFFFFFFFFu, s, o);
            sq += __shfl_xor_sync(0xFFFFFFFFu, sq, o);
        }
        if (tid == 0) { s_sum[0] = s; s_sq[0] = sq; }
    }
    __syncthreads();
    const float mu   = s_sum[0] * (1.0f / Dq);
    const float var  = s_sq[0] * (1.0f / Dq) - mu * mu;
    const float rstd = rsqrtf(var + 1e-5f);

    float4 g4 = *(const float4*)&g[tid * 4];
    float4 b4 = *(const float4*)&b[tid * 4];
    float4 r;
    r.x = (x4.x - mu) * rstd * g4.x + b4.x;
    r.y = (x4.y - mu) * rstd * g4.y + b4.y;
    r.z = (x4.z - mu) * rstd * g4.z + b4.z;
    r.w = (x4.w - mu) * rstd * g4.w + b4.w;
    *(float4*)&out[(size_t)row * Dq + tid * 4] = r;
}

// ---------------------------------------------------------------------------
// Launch
// ---------------------------------------------------------------------------
extern "C" void kernel_launch(void* const* d_in, const int* in_sizes, int n_in,
                              void* d_out, int out_size)
{
    (void)in_sizes; (void)n_in; (void)out_size;
    const float* x   = (const float*)d_in[0];
    const float* Wk  = (const float*)d_in[1];
    const float* bk  = (const float*)d_in[2];
    const float* Wv  = (const float*)d_in[3];
    const float* bv  = (const float*)d_in[4];
    const float* Wq  = (const float*)d_in[5];
    const float* bq  = (const float*)d_in[6];
    const float* Wkp = (const float*)d_in[7];
    const float* bkp = (const float*)d_in[8];
    const float* Wqp = (const float*)d_in[9];
    const float* bqp = (const float*)d_in[10];
    const float* ps  = (const float*)d_in[11];
    const float* lng = (const float*)d_in[12];
    const float* lnb = (const float*)d_in[13];
    const float* Wo  = (const float*)d_in[14];
    const float* bo  = (const float*)d_in[15];
    float* out = (float*)d_out;

    float *b0, *b1, *b2, *b3;
    cudaGetSymbolAddress((void**)&b0, g_buf0);
    cudaGetSymbolAddress((void**)&b1, g_buf1);
    cudaGetSymbolAddress((void**)&b2, g_buf2);
    cudaGetSymbolAddress((void**)&b3, g_buf3);

    const dim3 grid(Dq / 128, Mq / 128);   // (8, 128)
    const dim3 block(256);

    // key = x@Wk^T+bk -> b0 ; value -> b1 ; query -> b2
    sgemm_nt_kernel<false><<<grid, block>>>(x, Wk, bk, nullptr, b0, Mq, Dq, Dq);
    sgemm_nt_kernel<false><<<grid, block>>>(x, Wv, bv, nullptr, b1, Mq, Dq, Dq);
    sgemm_nt_kernel<false><<<grid, block>>>(x, Wq, bq, nullptr, b2, Mq, Dq, Dq);
    // kp_lin = key@Wkp^T+bkp -> b3 ; qp_lin = query@Wqp^T+bqp -> b0
    sgemm_nt_kernel<false><<<grid, block>>>(b0, Wkp, bkp, nullptr, b3, Mq, Dq, Dq);
    sgemm_nt_kernel<false><<<grid, block>>>(b2, Wqp, bqp, nullptr, b0, Mq, Dq, Dq);
    // phasor: (kp_lin=b3, qp_lin=b0, value=b1) -> retrieved in b2
    phasor_kernel<<<(Bq * NCHUNK * Dq) / 256, 256>>>(b3, b0, b1, ps, b2);
    // layernorm: b2 -> b1
    layernorm_kernel<<<Mq, 256>>>(b2, lng, lnb, b1);
    // out = x + b1@Wo^T + bo
    sgemm_nt_kernel<true><<<grid, block>>>(b1, Wo, bo, x, out, Mq, Dq, Dq);
}

// round 3
// speedup vs baseline: 2.2303x; 2.2303x over previous
#include <cuda_runtime.h>
#include <cuda_bf16.h>
#include <math.h>
#include <stdint.h>

// Problem constants
#define Bq 4
#define Sq 4096
#define Dq 1024
#define Mq (Bq * Sq)          // 16384 rows
#define CHUNKq 64
#define NCHUNK (Sq / CHUNKq)  // 64

// ---------------------------------------------------------------------------
// PTX helpers (compute_103-safe: cp.async + ldmatrix + mma.sync only)
// ---------------------------------------------------------------------------
__device__ __forceinline__ uint32_t smem_u32(const void* p) {
    uint32_t a;
    asm("{ .reg .u64 t; cvta.to.shared.u64 t, %1; cvt.u32.u64 %0, t; }" : "=r"(a) : "l"(p));
    return a;
}
#define CP_ASYNC16(dst, src) \
    asm volatile("cp.async.cg.shared.global [%0], [%1], 16;" :: "r"(dst), "l"(src))
#define CP_COMMIT() asm volatile("cp.async.commit_group;" ::: "memory")
#define CP_WAIT1()  asm volatile("cp.async.wait_group 1;" ::: "memory")

__device__ __forceinline__ void ldsm4(uint32_t* r, uint32_t addr) {
    asm volatile("ldmatrix.sync.aligned.m8n8.x4.shared.b16 {%0,%1,%2,%3}, [%4];"
                 : "=r"(r[0]), "=r"(r[1]), "=r"(r[2]), "=r"(r[3]) : "r"(addr));
}
__device__ __forceinline__ void mma_bf16(float* d, const uint32_t* a, uint32_t b0, uint32_t b1) {
    asm volatile(
        "mma.sync.aligned.m16n8k16.row.col.f32.bf16.bf16.f32 "
        "{%0,%1,%2,%3}, {%4,%5,%6,%7}, {%8,%9}, {%0,%1,%2,%3};"
        : "+f"(d[0]), "+f"(d[1]), "+f"(d[2]), "+f"(d[3])
        : "r"(a[0]), "r"(a[1]), "r"(a[2]), "r"(a[3]), "r"(b0), "r"(b1));
}

// ---------------------------------------------------------------------------
// Scratch (device globals — allocation-free per harness rules)
// ---------------------------------------------------------------------------
__device__ float g_f0[(size_t)Mq * Dq];   // value
__device__ float g_f1[(size_t)Mq * Dq];   // kp_lin
__device__ float g_f2[(size_t)Mq * Dq];   // qp_lin
__device__ float g_f3[(size_t)Mq * Dq];   // retrieved
__device__ __align__(256) __nv_bfloat16 g_xhi[(size_t)Mq * Dq];
__device__ __align__(256) __nv_bfloat16 g_xlo[(size_t)Mq * Dq];
__device__ __align__(256) __nv_bfloat16 g_ahi[(size_t)Mq * Dq];  // key, then ln
__device__ __align__(256) __nv_bfloat16 g_alo[(size_t)Mq * Dq];
__device__ __align__(256) __nv_bfloat16 g_bhi[(size_t)Mq * Dq];  // query
__device__ __align__(256) __nv_bfloat16 g_blo[(size_t)Mq * Dq];
__device__ __align__(256) __nv_bfloat16 g_whi[6 * (size_t)Dq * Dq];
__device__ __align__(256) __nv_bfloat16 g_wlo[6 * (size_t)Dq * Dq];

// ---------------------------------------------------------------------------
// fp32 -> (bf16 hi, bf16 lo) split, vectorized
// ---------------------------------------------------------------------------
__global__ __launch_bounds__(256)
void split_kernel(const float* __restrict__ in, __nv_bfloat16* __restrict__ hi,
                  __nv_bfloat16* __restrict__ lo)
{
    const size_t i4 = (size_t)blockIdx.x * blockDim.x + threadIdx.x;
    float4 v = *(const float4*)(in + i4 * 4);
    float f[4] = {v.x, v.y, v.z, v.w};
    unsigned short h[4], l[4];
#pragma unroll
    for (int j = 0; j < 4; j++) {
        __nv_bfloat16 hb = __float2bfloat16(f[j]);
        __nv_bfloat16 lb = __float2bfloat16(f[j] - __bfloat162float(hb));
        h[j] = *(unsigned short*)&hb;
        l[j] = *(unsigned short*)&lb;
    }
    uint2 hp, lp;
    hp.x = (uint32_t)h[0] | ((uint32_t)h[1] << 16);
    hp.y = (uint32_t)h[2] | ((uint32_t)h[3] << 16);
    lp.x = (uint32_t)l[0] | ((uint32_t)l[1] << 16);
    lp.y = (uint32_t)l[2] | ((uint32_t)l[3] << 16);
    *(uint2*)(hi + i4 * 4) = hp;
    *(uint2*)(lo + i4 * 4) = lp;
}

// ---------------------------------------------------------------------------
// Split-bf16 GEMM (NT) via mma.sync: C[m,n] = sum_k A[m,k]*W[n,k] + bias[n]
//   products: Ahi*Whi + Ahi*Wlo + Alo*Whi, fp32 accum.
// CTA tile 128x128, K-step 32, 3-stage cp.async pipeline, 8 warps (32x64 each).
// SMEM rows padded to 80B (5x16B chunks) -> conflict-free ldmatrix.
// ---------------------------------------------------------------------------
constexpr int TILE_B   = 10240;             // 128 rows * 80 B
constexpr int STAGE_B  = 4 * TILE_B;        // Ahi|Alo|Bhi|Blo
constexpr int SMEM_TOT = 3 * STAGE_B;       // 122880

__device__ __forceinline__ void load_stage(
    uint32_t sb_stage, int kb, int tid,
    const __nv_bfloat16* __restrict__ Ahi, const __nv_bfloat16* __restrict__ Alo,
    const __nv_bfloat16* __restrict__ Whi, const __nv_bfloat16* __restrict__ Wlo,
    int bm, int bn)
{
    const __nv_bfloat16* srcs[4] = {Ahi, Alo, Whi, Wlo};
    const int rb[4] = {bm, bm, bn, bn};
#pragma unroll
    for (int t = 0; t < 4; t++) {
#pragma unroll
        for (int i = 0; i < 2; i++) {
            const int idx = i * 256 + tid;     // 0..511
            const int row = idx >> 2;
            const int ch  = idx & 3;
            const __nv_bfloat16* g = srcs[t] + (((size_t)(rb[t] + row)) << 10) + kb * 32 + ch * 8;
            const uint32_t d = sb_stage + t * TILE_B + row * 80 + ch * 16;
            CP_ASYNC16(d, g);
        }
    }
}

template <bool OUT_BF16, bool RESID>
__global__ __launch_bounds__(256, 1)
void gemm_mma(const __nv_bfloat16* __restrict__ Ahi, const __nv_bfloat16* __restrict__ Alo,
              const __nv_bfloat16* __restrict__ Whi, const __nv_bfloat16* __restrict__ Wlo,
              const float* __restrict__ bias, const float* __restrict__ resid,
              float* __restrict__ Cf, __nv_bfloat16* __restrict__ Chi,
              __nv_bfloat16* __restrict__ Clo)
{
    extern __shared__ __align__(128) char smem[];
    const uint32_t sb = smem_u32(smem);
    const int tid  = threadIdx.x;
    const int wid  = tid >> 5;
    const int lane = tid & 31;
    const int bm = blockIdx.y * 128;
    const int bn = blockIdx.x * 128;
    const int wm = (wid >> 1) * 32;   // warp m offset in tile
    const int wn = (wid & 1) * 64;    // warp n offset in tile

    float acc[2][8][4];
#pragma unroll
    for (int i = 0; i < 2; i++)
#pragma unroll
        for (int j = 0; j < 8; j++)
#pragma unroll
            for (int k = 0; k < 4; k++) acc[i][j][k] = 0.0f;

    // prologue: stages 0,1
    load_stage(sb + 0 * STAGE_B, 0, tid, Ahi, Alo, Whi, Wlo, bm, bn);
    CP_COMMIT();
    load_stage(sb + 1 * STAGE_B, 1, tid, Ahi, Alo, Whi, Wlo, bm, bn);
    CP_COMMIT();

    const int sub = lane >> 3;
    const int rr  = lane & 7;

    for (int kb = 0; kb < 32; kb++) {
        CP_WAIT1();
        __syncthreads();
        if (kb + 2 < 32)
            load_stage(sb + ((kb + 2) % 3) * STAGE_B, kb + 2, tid, Ahi, Alo, Whi, Wlo, bm, bn);
        CP_COMMIT();

        const uint32_t st   = sb + (kb % 3) * STAGE_B;
        const uint32_t sAhi = st;
        const uint32_t sAlo = st + TILE_B;
        const uint32_t sBhi = st + 2 * TILE_B;
        const uint32_t sBlo = st + 3 * TILE_B;

#pragma unroll
        for (int kk = 0; kk < 2; kk++) {
            const int chunk = kk * 2 + (sub >> 1);
            uint32_t fahi[2][4], falo[2][4], fbhi[4][4], fblo[4][4];
#pragma unroll
            for (int mt = 0; mt < 2; mt++) {
                const int row = wm + mt * 16 + (sub & 1) * 8 + rr;
                const uint32_t off = row * 80 + chunk * 16;
                ldsm4(fahi[mt], sAhi + off);
                ldsm4(falo[mt], sAlo + off);
            }
#pragma unroll
            for (int g = 0; g < 4; g++) {
                const int row = wn + g * 16 + (sub & 1) * 8 + rr;
                const uint32_t off = row * 80 + chunk * 16;
                ldsm4(fbhi[g], sBhi + off);
                ldsm4(fblo[g], sBlo + off);
            }
#pragma unroll
            for (int mt = 0; mt < 2; mt++) {
#pragma unroll
                for (int g = 0; g < 4; g++) {
                    mma_bf16(acc[mt][2 * g],     fahi[mt], fbhi[g][0], fbhi[g][2]);
                    mma_bf16(acc[mt][2 * g],     fahi[mt], fblo[g][0], fblo[g][2]);
                    mma_bf16(acc[mt][2 * g],     falo[mt], fbhi[g][0], fbhi[g][2]);
                    mma_bf16(acc[mt][2 * g + 1], fahi[mt], fbhi[g][1], fbhi[g][3]);
                    mma_bf16(acc[mt][2 * g + 1], fahi[mt], fblo[g][1], fblo[g][3]);
                    mma_bf16(acc[mt][2 * g + 1], falo[mt], fbhi[g][1], fbhi[g][3]);
                }
            }
        }
    }

    // Epilogue: direct global stores with bias (+resid) (+bf16 split)
    const int qrow = lane >> 2;          // 0..7
    const int qcol = (lane & 3) * 2;     // 0,2,4,6
#pragma unroll
    for (int mt = 0; mt < 2; mt++) {
#pragma unroll
        for (int nt = 0; nt < 8; nt++) {
            const int col = bn + wn + nt * 8 + qcol;
            const float bz0 = __ldg(bias + col);
            const float bz1 = __ldg(bias + col + 1);
#pragma unroll
            for (int h = 0; h < 2; h++) {   // h=0: rows 0-7, h=1: rows 8-15
                const int row = bm + wm + mt * 16 + h * 8 + qrow;
                float v0 = acc[mt][nt][2 * h + 0] + bz0;
                float v1 = acc[mt][nt][2 * h + 1] + bz1;
                const size_t go = ((size_t)row << 10) + col;
                if (RESID) {
                    float2 x2 = *(const float2*)(resid + go);
                    v0 += x2.x; v1 += x2.y;
                }
                if (OUT_BF16) {
                    __nv_bfloat16 h0 = __float2bfloat16(v0);
                    __nv_bfloat16 h1 = __float2bfloat16(v1);
                    __nv_bfloat16 l0 = __float2bfloat16(v0 - __bfloat162float(h0));
                    __nv_bfloat16 l1 = __float2bfloat16(v1 - __bfloat162float(h1));
                    uint32_t hp = (uint32_t)(*(unsigned short*)&h0) | ((uint32_t)(*(unsigned short*)&h1) << 16);
                    uint32_t lp = (uint32_t)(*(unsigned short*)&l0) | ((uint32_t)(*(unsigned short*)&l1) << 16);
                    *(uint32_t*)(Chi + go) = hp;
                    *(uint32_t*)(Clo + go) = lp;
                } else {
                    float2 o; o.x = v0; o.y = v1;
                    *(float2*)(Cf + go) = o;
                }
            }
        }
    }
}

// ---------------------------------------------------------------------------
// Phasor kernel
// ---------------------------------------------------------------------------
__global__ void phasor_kernel(const float* __restrict__ kp_lin,
                              const float* __restrict__ qp_lin,
                              const float* __restrict__ val,
                              const float* __restrict__ phase_scale,
                              float* __restrict__ retrieved)
{
    const int idx = blockIdx.x * blockDim.x + threadIdx.x;
    const int d     = idx & (Dq - 1);
    const int chunk = (idx >> 10) & (NCHUNK - 1);
    const int b     = idx >> 16;
    const float ps  = phase_scale[d];
    size_t off = ((size_t)b * Sq + (size_t)chunk * CHUNKq) * Dq + d;

    float mr = 0.0f, mi = 0.0f;
#pragma unroll 4
    for (int s = 0; s < CHUNKq; s++) {
        const float kp = tanhf(kp_lin[off]) * ps;
        const float qp = tanhf(qp_lin[off]) * ps;
        const float v  = val[off];
        float skp, ckp, sqp, cqp;
        sincosf(kp, &skp, &ckp);
        sincosf(qp, &sqp, &cqp);
        mr = fmaf(v, ckp, mr);
        mi = fmaf(v, skp, mi);
        retrieved[off] = (mr * cqp + mi * sqp) * 0.03125f;
        off += Dq;
    }
}

// ---------------------------------------------------------------------------
// LayerNorm (1024) -> bf16 hi/lo split output
// ---------------------------------------------------------------------------
__global__ __launch_bounds__(256)
void layernorm_split_kernel(const float* __restrict__ in,
                            const float* __restrict__ g,
                            const float* __restrict__ b,
                            __nv_bfloat16* __restrict__ ohi,
                            __nv_bfloat16* __restrict__ olo)
{
    __shared__ float s_sum[8];
    __shared__ float s_sq[8];
    const int row = blockIdx.x;
    const int tid = threadIdx.x;
    const float* rin = in + (size_t)row * Dq;

    float4 x4 = *(const float4*)&rin[tid * 4];
    float s  = x4.x + x4.y + x4.z + x4.w;
    float sq = x4.x * x4.x + x4.y * x4.y + x4.z * x4.z + x4.w * x4.w;
#pragma unroll
    for (int o = 16; o > 0; o >>= 1) {
        s  += __shfl_xor_sync(0xFFFFFFFFu, s, o);
        sq += __shfl_xor_sync(0xFFFFFFFFu, sq, o);
    }
    const int warp = tid >> 5;
    if ((tid & 31) == 0) { s_sum[warp] = s; s_sq[warp] = sq; }
    __syncthreads();
    if (warp == 0) {
        s  = s_sum[tid & 7];
        sq = s_sq[tid & 7];
#pragma unroll
        for (int o = 4; o > 0; o >>= 1) {
            s  += __shfl_xor_sync(0xFFFFFFFFu, s, o);
            sq += __shfl_xor_sync(0xFFFFFFFFu, sq, o);
        }
        if (tid == 0) { s_sum[0] = s; s_sq[0] = sq; }
    }
    __syncthreads();
    const float mu   = s_sum[0] * (1.0f / Dq);
    const float var  = s_sq[0] * (1.0f / Dq) - mu * mu;
    const float rstd = rsqrtf(var + 1e-5f);

    float4 g4 = *(const float4*)&g[tid * 4];
    float4 b4 = *(const float4*)&b[tid * 4];
    float f[4];
    f[0] = (x4.x - mu) * rstd * g4.x + b4.x;
    f[1] = (x4.y - mu) * rstd * g4.y + b4.y;
    f[2] = (x4.z - mu) * rstd * g4.z + b4.z;
    f[3] = (x4.w - mu) * rstd * g4.w + b4.w;
    unsigned short h[4], l[4];
#pragma unroll
    for (int j = 0; j < 4; j++) {
        __nv_bfloat16 hb = __float2bfloat16(f[j]);
        __nv_bfloat16 lb = __float2bfloat16(f[j] - __bfloat162float(hb));
        h[j] = *(unsigned short*)&hb;
        l[j] = *(unsigned short*)&lb;
    }
    uint2 hp, lp;
    hp.x = (uint32_t)h[0] | ((uint32_t)h[1] << 16);
    hp.y = (uint32_t)h[2] | ((uint32_t)h[3] << 16);
    lp.x = (uint32_t)l[0] | ((uint32_t)l[1] << 16);
    lp.y = (uint32_t)l[2] | ((uint32_t)l[3] << 16);
    const size_t go = (size_t)row * Dq + tid * 4;
    *(uint2*)(ohi + go) = hp;
    *(uint2*)(olo + go) = lp;
}

// ---------------------------------------------------------------------------
// Launch
// ---------------------------------------------------------------------------
extern "C" void kernel_launch(void* const* d_in, const int* in_sizes, int n_in,
                              void* d_out, int out_size)
{
    (void)in_sizes; (void)n_in; (void)out_size;
    const float* x   = (const float*)d_in[0];
    const float* Wk  = (const float*)d_in[1];
    const float* bk  = (const float*)d_in[2];
    const float* Wv  = (const float*)d_in[3];
    const float* bv  = (const float*)d_in[4];
    const float* Wq  = (const float*)d_in[5];
    const float* bq  = (const float*)d_in[6];
    const float* Wkp = (const float*)d_in[7];
    const float* bkp = (const float*)d_in[8];
    const float* Wqp = (const float*)d_in[9];
    const float* bqp = (const float*)d_in[10];
    const float* ps  = (const float*)d_in[11];
    const float* lng = (const float*)d_in[12];
    const float* lnb = (const float*)d_in[13];
    const float* Wo  = (const float*)d_in[14];
    const float* bo  = (const float*)d_in[15];
    float* out = (float*)d_out;

    float *f0, *f1, *f2, *f3;
    __nv_bfloat16 *xhi, *xlo, *ahi, *alo, *bhi, *blo, *whi, *wlo;
    cudaGetSymbolAddress((void**)&f0, g_f0);
    cudaGetSymbolAddress((void**)&f1, g_f1);
    cudaGetSymbolAddress((void**)&f2, g_f2);
    cudaGetSymbolAddress((void**)&f3, g_f3);
    cudaGetSymbolAddress((void**)&xhi, g_xhi);
    cudaGetSymbolAddress((void**)&xlo, g_xlo);
    cudaGetSymbolAddress((void**)&ahi, g_ahi);
    cudaGetSymbolAddress((void**)&alo, g_alo);
    cudaGetSymbolAddress((void**)&bhi, g_bhi);
    cudaGetSymbolAddress((void**)&blo, g_blo);
    cudaGetSymbolAddress((void**)&whi, g_whi);
    cudaGetSymbolAddress((void**)&wlo, g_wlo);

    cudaFuncSetAttribute(gemm_mma<false, false>, cudaFuncAttributeMaxDynamicSharedMemorySize, SMEM_TOT);
    cudaFuncSetAttribute(gemm_mma<true, false>,  cudaFuncAttributeMaxDynamicSharedMemorySize, SMEM_TOT);
    cudaFuncSetAttribute(gemm_mma<false, true>,  cudaFuncAttributeMaxDynamicSharedMemorySize, SMEM_TOT);

    const size_t WN = (size_t)Dq * Dq;
    split_kernel<<<(Mq * Dq) / 1024, 256>>>(x, xhi, xlo);
    split_kernel<<<WN / 1024, 256>>>(Wk,  whi + 0 * WN, wlo + 0 * WN);
    split_kernel<<<WN / 1024, 256>>>(Wv,  whi + 1 * WN, wlo + 1 * WN);
    split_kernel<<<WN / 1024, 256>>>(Wq,  whi + 2 * WN, wlo + 2 * WN);
    split_kernel<<<WN / 1024, 256>>>(Wkp, whi + 3 * WN, wlo + 3 * WN);
    split_kernel<<<WN / 1024, 256>>>(Wqp, whi + 4 * WN, wlo + 4 * WN);
    split_kernel<<<WN / 1024, 256>>>(Wo,  whi + 5 * WN, wlo + 5 * WN);

    const dim3 grid(Dq / 128, Mq / 128);  // (8, 128)
    const dim3 block(256);

    // key -> bf16 (ahi/alo)
    gemm_mma<true, false><<<grid, block, SMEM_TOT>>>(xhi, xlo, whi + 0 * WN, wlo + 0 * WN, bk, nullptr, nullptr, ahi, alo);
    // value -> f32 (f0)
    gemm_mma<false, false><<<grid, block, SMEM_TOT>>>(xhi, xlo, whi + 1 * WN, wlo + 1 * WN, bv, nullptr, f0, nullptr, nullptr);
    // query -> bf16 (bhi/blo)
    gemm_mma<true, false><<<grid, block, SMEM_TOT>>>(xhi, xlo, whi + 2 * WN, wlo + 2 * WN, bq, nullptr, nullptr, bhi, blo);
    // kp_lin = key @ Wkp -> f1
    gemm_mma<false, false><<<grid, block, SMEM_TOT>>>(ahi, alo, whi + 3 * WN, wlo + 3 * WN, bkp, nullptr, f1, nullptr, nullptr);
    // qp_lin = query @ Wqp -> f2
    gemm_mma<false, false><<<grid, block, SMEM_TOT>>>(bhi, blo, whi + 4 * WN, wlo + 4 * WN, bqp, nullptr, f2, nullptr, nullptr);
    // phasor: (kp=f1, qp=f2, val=f0) -> f3
    phasor_kernel<<<(Bq * NCHUNK * Dq) / 256, 256>>>(f1, f2, f0, ps, f3);
    // layernorm f3 -> bf16 (reuse ahi/alo)
    layernorm_split_kernel<<<Mq, 256>>>(f3, lng, lnb, ahi, alo);
    // out = x + ln @ Wo + bo
    gemm_mma<false, true><<<grid, block, SMEM_TOT>>>(ahi, alo, whi + 5 * WN, wlo + 5 * WN, bo, x, out, nullptr, nullptr);
}

// round 4
// speedup vs baseline: 3.3073x; 1.4829x over previous
#include <cuda_runtime.h>
#include <cuda_fp16.h>
#include <math.h>
#include <stdint.h>

// Problem constants
#define Bq 4
#define Sq 4096
#define Dq 1024
#define Mq (Bq * Sq)          // 16384 rows
#define CHUNKq 64
#define NCHUNK (Sq / CHUNKq)  // 64

// ---------------------------------------------------------------------------
// PTX helpers (compute_103-safe)
// ---------------------------------------------------------------------------
__device__ __forceinline__ uint32_t smem_u32(const void* p) {
    uint32_t a;
    asm("{ .reg .u64 t; cvta.to.shared.u64 t, %1; cvt.u32.u64 %0, t; }" : "=r"(a) : "l"(p));
    return a;
}
#define CP_ASYNC16(dst, src) \
    asm volatile("cp.async.cg.shared.global [%0], [%1], 16;" :: "r"(dst), "l"(src))
#define CP_COMMIT() asm volatile("cp.async.commit_group;" ::: "memory")
#define CP_WAIT2()  asm volatile("cp.async.wait_group 2;" ::: "memory")

__device__ __forceinline__ void ldsm4(uint32_t* r, uint32_t addr) {
    asm volatile("ldmatrix.sync.aligned.m8n8.x4.shared.b16 {%0,%1,%2,%3}, [%4];"
                 : "=r"(r[0]), "=r"(r[1]), "=r"(r[2]), "=r"(r[3]) : "r"(addr));
}
__device__ __forceinline__ void mma_f16(float* d, const uint32_t* a, uint32_t b0, uint32_t b1) {
    asm volatile(
        "mma.sync.aligned.m16n8k16.row.col.f32.f16.f16.f32 "
        "{%0,%1,%2,%3}, {%4,%5,%6,%7}, {%8,%9}, {%0,%1,%2,%3};"
        : "+f"(d[0]), "+f"(d[1]), "+f"(d[2]), "+f"(d[3])
        : "r"(a[0]), "r"(a[1]), "r"(a[2]), "r"(a[3]), "r"(b0), "r"(b1));
}

// fast device math (phase is bounded to [-pi, pi] -> MUFU sin/cos are accurate)
__device__ __forceinline__ float ftanh(float x) {
    float e;
    asm("ex2.approx.f32 %0, %1;" : "=f"(e) : "f"(x * 2.8853900817779268f)); // e^(2x)
    float r;
    asm("rcp.approx.f32 %0, %1;" : "=f"(r) : "f"(e + 1.0f));
    return fmaf(-2.0f, r, 1.0f);
}
__device__ __forceinline__ float fsin(float x) { float r; asm("sin.approx.f32 %0, %1;" : "=f"(r) : "f"(x)); return r; }
__device__ __forceinline__ float fcos(float x) { float r; asm("cos.approx.f32 %0, %1;" : "=f"(r) : "f"(x)); return r; }

// ---------------------------------------------------------------------------
// Scratch (device globals — allocation-free per harness rules)
// ---------------------------------------------------------------------------
__device__ float g_f0[(size_t)Mq * Dq];   // value
__device__ float g_f1[(size_t)Mq * Dq];   // kp_lin
__device__ float g_f2[(size_t)Mq * Dq];   // qp_lin
__device__ float g_f3[(size_t)Mq * Dq];   // retrieved
__device__ __align__(256) __half g_xh[(size_t)Mq * Dq];   // x fp16
__device__ __align__(256) __half g_ah[(size_t)Mq * Dq];   // key fp16, then ln fp16
__device__ __align__(256) __half g_bh[(size_t)Mq * Dq];   // query fp16
__device__ __align__(256) __half g_whi[6 * (size_t)Dq * Dq];
__device__ __align__(256) __half g_wlo[6 * (size_t)Dq * Dq];

// ---------------------------------------------------------------------------
// fp32 -> fp16 convert (activations)
// ---------------------------------------------------------------------------
__global__ __launch_bounds__(256)
void convert_kernel(const float* __restrict__ in, __half* __restrict__ out)
{
    const size_t i4 = (size_t)blockIdx.x * blockDim.x + threadIdx.x;
    float4 v = *(const float4*)(in + i4 * 4);
    __half2 a = __floats2half2_rn(v.x, v.y);
    __half2 b = __floats2half2_rn(v.z, v.w);
    uint2 p;
    p.x = *(uint32_t*)&a;
    p.y = *(uint32_t*)&b;
    *(uint2*)(out + i4 * 4) = p;
}

// ---------------------------------------------------------------------------
// W*64 -> (fp16 hi, fp16 lo) split; GEMM epilogue divides by 64.
// Scaling by 64 keeps Wlo in fp16 normal range (|W| <= ~0.031 -> |W*64| <= 2).
// ---------------------------------------------------------------------------
__global__ __launch_bounds__(256)
void split_w_kernel(const float* __restrict__ in, __half* __restrict__ hi,
                    __half* __restrict__ lo)
{
    const size_t i4 = (size_t)blockIdx.x * blockDim.x + threadIdx.x;
    float4 v = *(const float4*)(in + i4 * 4);
    float f[4] = {v.x * 64.0f, v.y * 64.0f, v.z * 64.0f, v.w * 64.0f};
    __half h[4], l[4];
#pragma unroll
    for (int j = 0; j < 4; j++) {
        h[j] = __float2half_rn(f[j]);
        l[j] = __float2half_rn(f[j] - __half2float(h[j]));
    }
    uint2 hp, lp;
    hp.x = (uint32_t)(*(unsigned short*)&h[0]) | ((uint32_t)(*(unsigned short*)&h[1]) << 16);
    hp.y = (uint32_t)(*(unsigned short*)&h[2]) | ((uint32_t)(*(unsigned short*)&h[3]) << 16);
    lp.x = (uint32_t)(*(unsigned short*)&l[0]) | ((uint32_t)(*(unsigned short*)&l[1]) << 16);
    lp.y = (uint32_t)(*(unsigned short*)&l[2]) | ((uint32_t)(*(unsigned short*)&l[3]) << 16);
    *(uint2*)(hi + i4 * 4) = hp;
    *(uint2*)(lo + i4 * 4) = lp;
}

// ---------------------------------------------------------------------------
// fp16 2-product GEMM (NT): C = (A * (Whi + Wlo)) / 64 + bias (+resid)
// CTA 128x128, K-step 32, 4-stage cp.async, 8 warps (32x64 each).
// ---------------------------------------------------------------------------
constexpr int TILE_B   = 10240;             // 128 rows * 80 B
constexpr int STAGE_B  = 3 * TILE_B;        // A | Whi | Wlo
constexpr int SMEM_TOT = 4 * STAGE_B;       // 122880

__device__ __forceinline__ void load_stage(
    uint32_t sb_stage, int kb, int tid,
    const __half* __restrict__ A, const __half* __restrict__ Whi,
    const __half* __restrict__ Wlo, int bm, int bn)
{
    const __half* srcs[3] = {A, Whi, Wlo};
    const int rb[3] = {bm, bn, bn};
#pragma unroll
    for (int t = 0; t < 3; t++) {
#pragma unroll
        for (int i = 0; i < 2; i++) {
            const int idx = i * 256 + tid;     // 0..511
            const int row = idx >> 2;
            const int ch  = idx & 3;
            const __half* g = srcs[t] + (((size_t)(rb[t] + row)) << 10) + kb * 32 + ch * 8;
            const uint32_t d = sb_stage + t * TILE_B + row * 80 + ch * 16;
            CP_ASYNC16(d, g);
        }
    }
}

template <bool OUT_FP16, bool RESID>
__global__ __launch_bounds__(256, 1)
void gemm_mma(const __half* __restrict__ A,
              const __half* __restrict__ Whi, const __half* __restrict__ Wlo,
              const float* __restrict__ bias, const float* __restrict__ resid,
              float* __restrict__ Cf, __half* __restrict__ Ch)
{
    extern __shared__ __align__(128) char smem[];
    const uint32_t sb = smem_u32(smem);
    const int tid  = threadIdx.x;
    const int wid  = tid >> 5;
    const int lane = tid & 31;
    const int bm = blockIdx.y * 128;
    const int bn = blockIdx.x * 128;
    const int wm = (wid >> 1) * 32;   // warp m offset
    const int wn = (wid & 1) * 64;    // warp n offset

    float acc[2][8][4];
#pragma unroll
    for (int i = 0; i < 2; i++)
#pragma unroll
        for (int j = 0; j < 8; j++)
#pragma unroll
            for (int k = 0; k < 4; k++) acc[i][j][k] = 0.0f;

    // prologue: stages 0,1,2
    load_stage(sb + 0 * STAGE_B, 0, tid, A, Whi, Wlo, bm, bn); CP_COMMIT();
    load_stage(sb + 1 * STAGE_B, 1, tid, A, Whi, Wlo, bm, bn); CP_COMMIT();
    load_stage(sb + 2 * STAGE_B, 2, tid, A, Whi, Wlo, bm, bn); CP_COMMIT();

    const int sub = lane >> 3;
    const int rr  = lane & 7;

    for (int kb = 0; kb < 32; kb++) {
        CP_WAIT2();
        __syncthreads();
        if (kb + 3 < 32)
            load_stage(sb + ((kb + 3) & 3) * STAGE_B, kb + 3, tid, A, Whi, Wlo, bm, bn);
        CP_COMMIT();

        const uint32_t st   = sb + (kb & 3) * STAGE_B;
        const uint32_t sA   = st;
        const uint32_t sBhi = st + TILE_B;
        const uint32_t sBlo = st + 2 * TILE_B;

#pragma unroll
        for (int kk = 0; kk < 2; kk++) {
            const int chunk = kk * 2 + (sub >> 1);
            uint32_t fa[2][4], fbh[4][4], fbl[4][4];
#pragma unroll
            for (int mt = 0; mt < 2; mt++) {
                const int row = wm + mt * 16 + (sub & 1) * 8 + rr;
                ldsm4(fa[mt], sA + row * 80 + chunk * 16);
            }
#pragma unroll
            for (int g = 0; g < 4; g++) {
                const int row = wn + g * 16 + (sub & 1) * 8 + rr;
                const uint32_t off = row * 80 + chunk * 16;
                ldsm4(fbh[g], sBhi + off);
                ldsm4(fbl[g], sBlo + off);
            }
#pragma unroll
            for (int mt = 0; mt < 2; mt++) {
#pragma unroll
                for (int g = 0; g < 4; g++) {
                    mma_f16(acc[mt][2 * g],     fa[mt], fbh[g][0], fbh[g][2]);
                    mma_f16(acc[mt][2 * g],     fa[mt], fbl[g][0], fbl[g][2]);
                    mma_f16(acc[mt][2 * g + 1], fa[mt], fbh[g][1], fbh[g][3]);
                    mma_f16(acc[mt][2 * g + 1], fa[mt], fbl[g][1], fbl[g][3]);
                }
            }
        }
    }

    // Epilogue: scale 1/64, bias (+resid), store fp32 or fp16
    const int qrow = lane >> 2;
    const int qcol = (lane & 3) * 2;
#pragma unroll
    for (int mt = 0; mt < 2; mt++) {
#pragma unroll
        for (int nt = 0; nt < 8; nt++) {
            const int col = bn + wn + nt * 8 + qcol;
            const float bz0 = __ldg(bias + col);
            const float bz1 = __ldg(bias + col + 1);
#pragma unroll
            for (int h = 0; h < 2; h++) {
                const int row = bm + wm + mt * 16 + h * 8 + qrow;
                float v0 = acc[mt][nt][2 * h + 0] * 0.015625f + bz0;
                float v1 = acc[mt][nt][2 * h + 1] * 0.015625f + bz1;
                const size_t go = ((size_t)row << 10) + col;
                if (RESID) {
                    float2 x2 = *(const float2*)(resid + go);
                    v0 += x2.x; v1 += x2.y;
                }
                if (OUT_FP16) {
                    __half2 hv = __floats2half2_rn(v0, v1);
                    *(uint32_t*)(Ch + go) = *(uint32_t*)&hv;
                } else {
                    float2 o; o.x = v0; o.y = v1;
                    *(float2*)(Cf + go) = o;
                }
            }
        }
    }
}

// ---------------------------------------------------------------------------
// Phasor kernel with MUFU fast math
// ---------------------------------------------------------------------------
__global__ void phasor_kernel(const float* __restrict__ kp_lin,
                              const float* __restrict__ qp_lin,
                              const float* __restrict__ val,
                              const float* __restrict__ phase_scale,
                              float* __restrict__ retrieved)
{
    const int idx = blockIdx.x * blockDim.x + threadIdx.x;
    const int d     = idx & (Dq - 1);
    const int chunk = (idx >> 10) & (NCHUNK - 1);
    const int b     = idx >> 16;
    const float ps  = phase_scale[d];
    size_t off = ((size_t)b * Sq + (size_t)chunk * CHUNKq) * Dq + d;

    float mr = 0.0f, mi = 0.0f;
#pragma unroll 4
    for (int s = 0; s < CHUNKq; s++) {
        const float kp = ftanh(kp_lin[off]) * ps;
        const float qp = ftanh(qp_lin[off]) * ps;
        const float v  = val[off];
        mr = fmaf(v, fcos(kp), mr);
        mi = fmaf(v, fsin(kp), mi);
        retrieved[off] = (mr * fcos(qp) + mi * fsin(qp)) * 0.03125f;
        off += Dq;
    }
}

// ---------------------------------------------------------------------------
// LayerNorm (1024) -> fp16 output
// ---------------------------------------------------------------------------
__global__ __launch_bounds__(256)
void layernorm_kernel(const float* __restrict__ in,
                      const float* __restrict__ g,
                      const float* __restrict__ b,
                      __half* __restrict__ outh)
{
    __shared__ float s_sum[8];
    __shared__ float s_sq[8];
    const int row = blockIdx.x;
    const int tid = threadIdx.x;
    const float* rin = in + (size_t)row * Dq;

    float4 x4 = *(const float4*)&rin[tid * 4];
    float s  = x4.x + x4.y + x4.z + x4.w;
    float sq = x4.x * x4.x + x4.y * x4.y + x4.z * x4.z + x4.w * x4.w;
#pragma unroll
    for (int o = 16; o > 0; o >>= 1) {
        s  += __shfl_xor_sync(0xFFFFFFFFu, s, o);
        sq += __shfl_xor_sync(0xFFFFFFFFu, sq, o);
    }
    const int warp = tid >> 5;
    if ((tid & 31) == 0) { s_sum[warp] = s; s_sq[warp] = sq; }
    __syncthreads();
    if (warp == 0) {
        s  = s_sum[tid & 7];
        sq = s_sq[tid & 7];
#pragma unroll
        for (int o = 4; o > 0; o >>= 1) {
            s  += __shfl_xor_sync(0xFFFFFFFFu, s, o);
            sq += __shfl_xor_sync(0xFFFFFFFFu, sq, o);
        }
        if (tid == 0) { s_sum[0] = s; s_sq[0] = sq; }
    }
    __syncthreads();
    const float mu   = s_sum[0] * (1.0f / Dq);
    const float var  = s_sq[0] * (1.0f / Dq) - mu * mu;
    const float rstd = rsqrtf(var + 1e-5f);

    float4 g4 = *(const float4*)&g[tid * 4];
    float4 b4 = *(const float4*)&b[tid * 4];
    __half2 h0 = __floats2half2_rn((x4.x - mu) * rstd * g4.x + b4.x,
                                   (x4.y - mu) * rstd * g4.y + b4.y);
    __half2 h1 = __floats2half2_rn((x4.z - mu) * rstd * g4.z + b4.z,
                                   (x4.w - mu) * rstd * g4.w + b4.w);
    uint2 p;
    p.x = *(uint32_t*)&h0;
    p.y = *(uint32_t*)&h1;
    *(uint2*)(outh + (size_t)row * Dq + tid * 4) = p;
}

// ---------------------------------------------------------------------------
// Launch
// ---------------------------------------------------------------------------
extern "C" void kernel_launch(void* const* d_in, const int* in_sizes, int n_in,
                              void* d_out, int out_size)
{
    (void)in_sizes; (void)n_in; (void)out_size;
    const float* x   = (const float*)d_in[0];
    const float* Wk  = (const float*)d_in[1];
    const float* bk  = (const float*)d_in[2];
    const float* Wv  = (const float*)d_in[3];
    const float* bv  = (const float*)d_in[4];
    const float* Wq  = (const float*)d_in[5];
    const float* bq  = (const float*)d_in[6];
    const float* Wkp = (const float*)d_in[7];
    const float* bkp = (const float*)d_in[8];
    const float* Wqp = (const float*)d_in[9];
    const float* bqp = (const float*)d_in[10];
    const float* ps  = (const float*)d_in[11];
    const float* lng = (const float*)d_in[12];
    const float* lnb = (const float*)d_in[13];
    const float* Wo  = (const float*)d_in[14];
    const float* bo  = (const float*)d_in[15];
    float* out = (float*)d_out;

    float *f0, *f1, *f2, *f3;
    __half *xh, *ah, *bh, *whi, *wlo;
    cudaGetSymbolAddress((void**)&f0, g_f0);
    cudaGetSymbolAddress((void**)&f1, g_f1);
    cudaGetSymbolAddress((void**)&f2, g_f2);
    cudaGetSymbolAddress((void**)&f3, g_f3);
    cudaGetSymbolAddress((void**)&xh, g_xh);
    cudaGetSymbolAddress((void**)&ah, g_ah);
    cudaGetSymbolAddress((void**)&bh, g_bh);
    cudaGetSymbolAddress((void**)&whi, g_whi);
    cudaGetSymbolAddress((void**)&wlo, g_wlo);

    cudaFuncSetAttribute(gemm_mma<false, false>, cudaFuncAttributeMaxDynamicSharedMemorySize, SMEM_TOT);
    cudaFuncSetAttribute(gemm_mma<true, false>,  cudaFuncAttributeMaxDynamicSharedMemorySize, SMEM_TOT);
    cudaFuncSetAttribute(gemm_mma<false, true>,  cudaFuncAttributeMaxDynamicSharedMemorySize, SMEM_TOT);

    const size_t WN = (size_t)Dq * Dq;
    convert_kernel<<<(Mq * Dq) / 1024, 256>>>(x, xh);
    split_w_kernel<<<WN / 1024, 256>>>(Wk,  whi + 0 * WN, wlo + 0 * WN);
    split_w_kernel<<<WN / 1024, 256>>>(Wv,  whi + 1 * WN, wlo + 1 * WN);
    split_w_kernel<<<WN / 1024, 256>>>(Wq,  whi + 2 * WN, wlo + 2 * WN);
    split_w_kernel<<<WN / 1024, 256>>>(Wkp, whi + 3 * WN, wlo + 3 * WN);
    split_w_kernel<<<WN / 1024, 256>>>(Wqp, whi + 4 * WN, wlo + 4 * WN);
    split_w_kernel<<<WN / 1024, 256>>>(Wo,  whi + 5 * WN, wlo + 5 * WN);

    const dim3 grid(Dq / 128, Mq / 128);  // (8, 128)
    const dim3 block(256);

    // key -> fp16 (ah)
    gemm_mma<true, false><<<grid, block, SMEM_TOT>>>(xh, whi + 0 * WN, wlo + 0 * WN, bk, nullptr, nullptr, ah);
    // value -> f32 (f0)
    gemm_mma<false, false><<<grid, block, SMEM_TOT>>>(xh, whi + 1 * WN, wlo + 1 * WN, bv, nullptr, f0, nullptr);
    // query -> fp16 (bh)
    gemm_mma<true, false><<<grid, block, SMEM_TOT>>>(xh, whi + 2 * WN, wlo + 2 * WN, bq, nullptr, nullptr, bh);
    // kp_lin = key @ Wkp -> f1
    gemm_mma<false, false><<<grid, block, SMEM_TOT>>>(ah, whi + 3 * WN, wlo + 3 * WN, bkp, nullptr, f1, nullptr);
    // qp_lin = query @ Wqp -> f2
    gemm_mma<false, false><<<grid, block, SMEM_TOT>>>(bh, whi + 4 * WN, wlo + 4 * WN, bqp, nullptr, f2, nullptr);
    // phasor: (kp=f1, qp=f2, val=f0) -> f3
    phasor_kernel<<<(Bq * NCHUNK * Dq) / 256, 256>>>(f1, f2, f0, ps, f3);
    // layernorm f3 -> fp16 (reuse ah)
    layernorm_kernel<<<Mq, 256>>>(f3, lng, lnb, ah);
    // out = x + ln @ Wo + bo
    gemm_mma<false, true><<<grid, block, SMEM_TOT>>>(ah, whi + 5 * WN, wlo + 5 * WN, bo, x, out, nullptr);
}

// round 5
// speedup vs baseline: 6.1944x; 1.8730x over previous
#include <cuda_runtime.h>
#include <cuda_fp16.h>
#include <math.h>
#include <stdint.h>

// Problem constants
#define Bq 4
#define Sq 4096
#define Dq 1024
#define Mq (Bq * Sq)          // 16384 rows
#define CHUNKq 64
#define NCHUNK (Sq / CHUNKq)  // 64

// ---------------------------------------------------------------------------
// PTX helpers (compute_103-safe)
// ---------------------------------------------------------------------------
__device__ __forceinline__ uint32_t smem_u32(const void* p) {
    uint32_t a;
    asm("{ .reg .u64 t; cvta.to.shared.u64 t, %1; cvt.u32.u64 %0, t; }" : "=r"(a) : "l"(p));
    return a;
}
#define CP_ASYNC16(dst, src) \
    asm volatile("cp.async.cg.shared.global [%0], [%1], 16;" :: "r"(dst), "l"(src))
#define CP_COMMIT() asm volatile("cp.async.commit_group;" ::: "memory")
#define CP_WAIT2()  asm volatile("cp.async.wait_group 2;" ::: "memory")

__device__ __forceinline__ void ldsm4(uint32_t* r, uint32_t addr) {
    asm volatile("ldmatrix.sync.aligned.m8n8.x4.shared.b16 {%0,%1,%2,%3}, [%4];"
                 : "=r"(r[0]), "=r"(r[1]), "=r"(r[2]), "=r"(r[3]) : "r"(addr));
}
__device__ __forceinline__ void mma_f16(float* d, const uint32_t* a, uint32_t b0, uint32_t b1) {
    asm volatile(
        "mma.sync.aligned.m16n8k16.row.col.f32.f16.f16.f32 "
        "{%0,%1,%2,%3}, {%4,%5,%6,%7}, {%8,%9}, {%0,%1,%2,%3};"
        : "+f"(d[0]), "+f"(d[1]), "+f"(d[2]), "+f"(d[3])
        : "r"(a[0]), "r"(a[1]), "r"(a[2]), "r"(a[3]), "r"(b0), "r"(b1));
}

// fast device math (phase bounded to [-pi, pi] -> MUFU sin/cos accurate)
__device__ __forceinline__ float ftanh(float x) {
    float e;
    asm("ex2.approx.f32 %0, %1;" : "=f"(e) : "f"(x * 2.8853900817779268f)); // e^(2x)
    float r;
    asm("rcp.approx.f32 %0, %1;" : "=f"(r) : "f"(e + 1.0f));
    return fmaf(-2.0f, r, 1.0f);
}
__device__ __forceinline__ float fsin(float x) { float r; asm("sin.approx.f32 %0, %1;" : "=f"(r) : "f"(x)); return r; }
__device__ __forceinline__ float fcos(float x) { float r; asm("cos.approx.f32 %0, %1;" : "=f"(r) : "f"(x)); return r; }

// ---------------------------------------------------------------------------
// Scratch (device globals — allocation-free per harness rules)
// ---------------------------------------------------------------------------
__device__ float g_f0[(size_t)Mq * Dq];   // value
__device__ float g_f1[(size_t)Mq * Dq];   // kp_lin
__device__ float g_f2[(size_t)Mq * Dq];   // qp_lin
__device__ float g_f3[(size_t)Mq * Dq];   // retrieved
__device__ __align__(256) __half g_xh[(size_t)Mq * Dq];   // x fp16
__device__ __align__(256) __half g_ah[(size_t)Mq * Dq];   // key fp16, then ln fp16
__device__ __align__(256) __half g_bh[(size_t)Mq * Dq];   // query fp16
__device__ __align__(256) __half g_wh[6 * (size_t)Dq * Dq];

// ---------------------------------------------------------------------------
// fp32 -> fp16 convert (activations)
// ---------------------------------------------------------------------------
__global__ __launch_bounds__(256)
void convert_kernel(const float* __restrict__ in, __half* __restrict__ out)
{
    const size_t i4 = (size_t)blockIdx.x * blockDim.x + threadIdx.x;
    float4 v = *(const float4*)(in + i4 * 4);
    __half2 a = __floats2half2_rn(v.x, v.y);
    __half2 b = __floats2half2_rn(v.z, v.w);
    uint2 p;
    p.x = *(uint32_t*)&a;
    p.y = *(uint32_t*)&b;
    *(uint2*)(out + i4 * 4) = p;
}

// W*64 -> fp16 (scale keeps values well inside fp16 normal range; epilogue /64)
__global__ __launch_bounds__(256)
void convert_w64_kernel(const float* __restrict__ in, __half* __restrict__ out)
{
    const size_t i4 = (size_t)blockIdx.x * blockDim.x + threadIdx.x;
    float4 v = *(const float4*)(in + i4 * 4);
    __half2 a = __floats2half2_rn(v.x * 64.0f, v.y * 64.0f);
    __half2 b = __floats2half2_rn(v.z * 64.0f, v.w * 64.0f);
    uint2 p;
    p.x = *(uint32_t*)&a;
    p.y = *(uint32_t*)&b;
    *(uint2*)(out + i4 * 4) = p;
}

// ---------------------------------------------------------------------------
// fp16 single-product GEMM (NT): C = (A * W64) / 64 + bias (+resid)
// CTA 128x128, K-step 32, 4-stage cp.async, 8 warps (32x64 each), 2 CTAs/SM.
// ---------------------------------------------------------------------------
constexpr int TILE_B   = 10240;             // 128 rows * 80 B
constexpr int STAGE_B  = 2 * TILE_B;        // A | W
constexpr int SMEM_TOT = 4 * STAGE_B;       // 81920

__device__ __forceinline__ void load_stage(
    uint32_t sb_stage, int kb, int tid,
    const __half* __restrict__ A, const __half* __restrict__ W, int bm, int bn)
{
    const __half* srcs[2] = {A, W};
    const int rb[2] = {bm, bn};
#pragma unroll
    for (int t = 0; t < 2; t++) {
#pragma unroll
        for (int i = 0; i < 2; i++) {
            const int idx = i * 256 + tid;     // 0..511
            const int row = idx >> 2;
            const int ch  = idx & 3;
            const __half* g = srcs[t] + (((size_t)(rb[t] + row)) << 10) + kb * 32 + ch * 8;
            const uint32_t d = sb_stage + t * TILE_B + row * 80 + ch * 16;
            CP_ASYNC16(d, g);
        }
    }
}

template <bool OUT_FP16, bool RESID>
__global__ __launch_bounds__(256, 2)
void gemm_mma(const __half* __restrict__ A, const __half* __restrict__ W,
              const float* __restrict__ bias, const float* __restrict__ resid,
              float* __restrict__ Cf, __half* __restrict__ Ch)
{
    extern __shared__ __align__(128) char smem[];
    const uint32_t sb = smem_u32(smem);
    const int tid  = threadIdx.x;
    const int wid  = tid >> 5;
    const int lane = tid & 31;
    const int bm = blockIdx.y * 128;
    const int bn = blockIdx.x * 128;
    const int wm = (wid >> 1) * 32;   // warp m offset
    const int wn = (wid & 1) * 64;    // warp n offset

    float acc[2][8][4];
#pragma unroll
    for (int i = 0; i < 2; i++)
#pragma unroll
        for (int j = 0; j < 8; j++)
#pragma unroll
            for (int k = 0; k < 4; k++) acc[i][j][k] = 0.0f;

    load_stage(sb + 0 * STAGE_B, 0, tid, A, W, bm, bn); CP_COMMIT();
    load_stage(sb + 1 * STAGE_B, 1, tid, A, W, bm, bn); CP_COMMIT();
    load_stage(sb + 2 * STAGE_B, 2, tid, A, W, bm, bn); CP_COMMIT();

    const int sub = lane >> 3;
    const int rr  = lane & 7;

    for (int kb = 0; kb < 32; kb++) {
        CP_WAIT2();
        __syncthreads();
        if (kb + 3 < 32)
            load_stage(sb + ((kb + 3) & 3) * STAGE_B, kb + 3, tid, A, W, bm, bn);
        CP_COMMIT();

        const uint32_t st = sb + (kb & 3) * STAGE_B;
        const uint32_t sA = st;
        const uint32_t sB = st + TILE_B;

#pragma unroll
        for (int kk = 0; kk < 2; kk++) {
            const int chunk = kk * 2 + (sub >> 1);
            uint32_t fa[2][4], fb[4][4];
#pragma unroll
            for (int mt = 0; mt < 2; mt++) {
                const int row = wm + mt * 16 + (sub & 1) * 8 + rr;
                ldsm4(fa[mt], sA + row * 80 + chunk * 16);
            }
#pragma unroll
            for (int g = 0; g < 4; g++) {
                const int row = wn + g * 16 + (sub & 1) * 8 + rr;
                ldsm4(fb[g], sB + row * 80 + chunk * 16);
            }
#pragma unroll
            for (int mt = 0; mt < 2; mt++) {
#pragma unroll
                for (int g = 0; g < 4; g++) {
                    mma_f16(acc[mt][2 * g],     fa[mt], fb[g][0], fb[g][2]);
                    mma_f16(acc[mt][2 * g + 1], fa[mt], fb[g][1], fb[g][3]);
                }
            }
        }
    }

    // Epilogue: scale 1/64, bias (+resid), store fp32 or fp16
    const int qrow = lane >> 2;
    const int qcol = (lane & 3) * 2;
#pragma unroll
    for (int mt = 0; mt < 2; mt++) {
#pragma unroll
        for (int nt = 0; nt < 8; nt++) {
            const int col = bn + wn + nt * 8 + qcol;
            const float bz0 = __ldg(bias + col);
            const float bz1 = __ldg(bias + col + 1);
#pragma unroll
            for (int h = 0; h < 2; h++) {
                const int row = bm + wm + mt * 16 + h * 8 + qrow;
                float v0 = acc[mt][nt][2 * h + 0] * 0.015625f + bz0;
                float v1 = acc[mt][nt][2 * h + 1] * 0.015625f + bz1;
                const size_t go = ((size_t)row << 10) + col;
                if (RESID) {
                    float2 x2 = *(const float2*)(resid + go);
                    v0 += x2.x; v1 += x2.y;
                }
                if (OUT_FP16) {
                    __half2 hv = __floats2half2_rn(v0, v1);
                    *(uint32_t*)(Ch + go) = *(uint32_t*)&hv;
                } else {
                    float2 o; o.x = v0; o.y = v1;
                    *(float2*)(Cf + go) = o;
                }
            }
        }
    }
}

// ---------------------------------------------------------------------------
// Phasor kernel with MUFU fast math
// ---------------------------------------------------------------------------
__global__ void phasor_kernel(const float* __restrict__ kp_lin,
                              const float* __restrict__ qp_lin,
                              const float* __restrict__ val,
                              const float* __restrict__ phase_scale,
                              float* __restrict__ retrieved)
{
    const int idx = blockIdx.x * blockDim.x + threadIdx.x;
    const int d     = idx & (Dq - 1);
    const int chunk = (idx >> 10) & (NCHUNK - 1);
    const int b     = idx >> 16;
    const float ps  = phase_scale[d];
    size_t off = ((size_t)b * Sq + (size_t)chunk * CHUNKq) * Dq + d;

    float mr = 0.0f, mi = 0.0f;
#pragma unroll 4
    for (int s = 0; s < CHUNKq; s++) {
        const float kp = ftanh(kp_lin[off]) * ps;
        const float qp = ftanh(qp_lin[off]) * ps;
        const float v  = val[off];
        mr = fmaf(v, fcos(kp), mr);
        mi = fmaf(v, fsin(kp), mi);
        retrieved[off] = (mr * fcos(qp) + mi * fsin(qp)) * 0.03125f;
        off += Dq;
    }
}

// ---------------------------------------------------------------------------
// LayerNorm (1024) -> fp16 output
// ---------------------------------------------------------------------------
__global__ __launch_bounds__(256)
void layernorm_kernel(const float* __restrict__ in,
                      const float* __restrict__ g,
                      const float* __restrict__ b,
                      __half* __restrict__ outh)
{
    __shared__ float s_sum[8];
    __shared__ float s_sq[8];
    const int row = blockIdx.x;
    const int tid = threadIdx.x;
    const float* rin = in + (size_t)row * Dq;

    float4 x4 = *(const float4*)&rin[tid * 4];
    float s  = x4.x + x4.y + x4.z + x4.w;
    float sq = x4.x * x4.x + x4.y * x4.y + x4.z * x4.z + x4.w * x4.w;
#pragma unroll
    for (int o = 16; o > 0; o >>= 1) {
        s  += __shfl_xor_sync(0xFFFFFFFFu, s, o);
        sq += __shfl_xor_sync(0xFFFFFFFFu, sq, o);
    }
    const int warp = tid >> 5;
    if ((tid & 31) == 0) { s_sum[warp] = s; s_sq[warp] = sq; }
    __syncthreads();
    if (warp == 0) {
        s  = s_sum[tid & 7];
        sq = s_sq[tid & 7];
#pragma unroll
        for (int o = 4; o > 0; o >>= 1) {
            s  += __shfl_xor_sync(0xFFFFFFFFu, s, o);
            sq += __shfl_xor_sync(0xFFFFFFFFu, sq, o);
        }
        if (tid == 0) { s_sum[0] = s; s_sq[0] = sq; }
    }
    __syncthreads();
    const float mu   = s_sum[0] * (1.0f / Dq);
    const float var  = s_sq[0] * (1.0f / Dq) - mu * mu;
    const float rstd = rsqrtf(var + 1e-5f);

    float4 g4 = *(const float4*)&g[tid * 4];
    float4 b4 = *(const float4*)&b[tid * 4];
    __half2 h0 = __floats2half2_rn((x4.x - mu) * rstd * g4.x + b4.x,
                                   (x4.y - mu) * rstd * g4.y + b4.y);
    __half2 h1 = __floats2half2_rn((x4.z - mu) * rstd * g4.z + b4.z,
                                   (x4.w - mu) * rstd * g4.w + b4.w);
    uint2 p;
    p.x = *(uint32_t*)&h0;
    p.y = *(uint32_t*)&h1;
    *(uint2*)(outh + (size_t)row * Dq + tid * 4) = p;
}

// ---------------------------------------------------------------------------
// Launch
// ---------------------------------------------------------------------------
extern "C" void kernel_launch(void* const* d_in, const int* in_sizes, int n_in,
                              void* d_out, int out_size)
{
    (void)in_sizes; (void)n_in; (void)out_size;
    const float* x   = (const float*)d_in[0];
    const float* Wk  = (const float*)d_in[1];
    const float* bk  = (const float*)d_in[2];
    const float* Wv  = (const float*)d_in[3];
    const float* bv  = (const float*)d_in[4];
    const float* Wq  = (const float*)d_in[5];
    const float* bq  = (const float*)d_in[6];
    const float* Wkp = (const float*)d_in[7];
    const float* bkp = (const float*)d_in[8];
    const float* Wqp = (const float*)d_in[9];
    const float* bqp = (const float*)d_in[10];
    const float* ps  = (const float*)d_in[11];
    const float* lng = (const float*)d_in[12];
    const float* lnb = (const float*)d_in[13];
    const float* Wo  = (const float*)d_in[14];
    const float* bo  = (const float*)d_in[15];
    float* out = (float*)d_out;

    float *f0, *f1, *f2, *f3;
    __half *xh, *ah, *bh, *wh;
    cudaGetSymbolAddress((void**)&f0, g_f0);
    cudaGetSymbolAddress((void**)&f1, g_f1);
    cudaGetSymbolAddress((void**)&f2, g_f2);
    cudaGetSymbolAddress((void**)&f3, g_f3);
    cudaGetSymbolAddress((void**)&xh, g_xh);
    cudaGetSymbolAddress((void**)&ah, g_ah);
    cudaGetSymbolAddress((void**)&bh, g_bh);
    cudaGetSymbolAddress((void**)&wh, g_wh);

    cudaFuncSetAttribute(gemm_mma<false, false>, cudaFuncAttributeMaxDynamicSharedMemorySize, SMEM_TOT);
    cudaFuncSetAttribute(gemm_mma<true, false>,  cudaFuncAttributeMaxDynamicSharedMemorySize, SMEM_TOT);
    cudaFuncSetAttribute(gemm_mma<false, true>,  cudaFuncAttributeMaxDynamicSharedMemorySize, SMEM_TOT);

    const size_t WN = (size_t)Dq * Dq;
    convert_kernel<<<(Mq * Dq) / 1024, 256>>>(x, xh);
    convert_w64_kernel<<<WN / 1024, 256>>>(Wk,  wh + 0 * WN);
    convert_w64_kernel<<<WN / 1024, 256>>>(Wv,  wh + 1 * WN);
    convert_w64_kernel<<<WN / 1024, 256>>>(Wq,  wh + 2 * WN);
    convert_w64_kernel<<<WN / 1024, 256>>>(Wkp, wh + 3 * WN);
    convert_w64_kernel<<<WN / 1024, 256>>>(Wqp, wh + 4 * WN);
    convert_w64_kernel<<<WN / 1024, 256>>>(Wo,  wh + 5 * WN);

    const dim3 grid(Dq / 128, Mq / 128);  // (8, 128)
    const dim3 block(256);

    // key -> fp16 (ah)
    gemm_mma<true, false><<<grid, block, SMEM_TOT>>>(xh, wh + 0 * WN, bk, nullptr, nullptr, ah);
    // value -> f32 (f0)
    gemm_mma<false, false><<<grid, block, SMEM_TOT>>>(xh, wh + 1 * WN, bv, nullptr, f0, nullptr);
    // query -> fp16 (bh)
    gemm_mma<true, false><<<grid, block, SMEM_TOT>>>(xh, wh + 2 * WN, bq, nullptr, nullptr, bh);
    // kp_lin = key @ Wkp -> f1
    gemm_mma<false, false><<<grid, block, SMEM_TOT>>>(ah, wh + 3 * WN, bkp, nullptr, f1, nullptr);
    // qp_lin = query @ Wqp -> f2
    gemm_mma<false, false><<<grid, block, SMEM_TOT>>>(bh, wh + 4 * WN, bqp, nullptr, f2, nullptr);
    // phasor: (kp=f1, qp=f2, val=f0) -> f3
    phasor_kernel<<<(Bq * NCHUNK * Dq) / 256, 256>>>(f1, f2, f0, ps, f3);
    // layernorm f3 -> fp16 (reuse ah)
    layernorm_kernel<<<Mq, 256>>>(f3, lng, lnb, ah);
    // out = x + ln @ Wo + bo
    gemm_mma<false, true><<<grid, block, SMEM_TOT>>>(ah, wh + 5 * WN, bo, x, out, nullptr);
}

// round 6
// speedup vs baseline: 7.9884x; 1.2896x over previous
#include <cuda_runtime.h>
#include <cuda_fp16.h>
#include <math.h>
#include <stdint.h>

// Problem constants
#define Bq 4
#define Sq 4096
#define Dq 1024
#define Mq (Bq * Sq)          // 16384 rows
#define CHUNKq 64
#define NCHUNK (Sq / CHUNKq)  // 64

// ---------------------------------------------------------------------------
// PTX helpers (compute_103-safe)
// ---------------------------------------------------------------------------
__device__ __forceinline__ uint32_t smem_u32(const void* p) {
    uint32_t a;
    asm("{ .reg .u64 t; cvta.to.shared.u64 t, %1; cvt.u32.u64 %0, t; }" : "=r"(a) : "l"(p));
    return a;
}
#define CP_ASYNC16(dst, src) \
    asm volatile("cp.async.cg.shared.global [%0], [%1], 16;" :: "r"(dst), "l"(src))
#define CP_COMMIT() asm volatile("cp.async.commit_group;" ::: "memory")
#define CP_WAIT2()  asm volatile("cp.async.wait_group 2;" ::: "memory")

__device__ __forceinline__ void ldsm4(uint32_t* r, uint32_t addr) {
    asm volatile("ldmatrix.sync.aligned.m8n8.x4.shared.b16 {%0,%1,%2,%3}, [%4];"
                 : "=r"(r[0]), "=r"(r[1]), "=r"(r[2]), "=r"(r[3]) : "r"(addr));
}
__device__ __forceinline__ void mma_f16(float* d, const uint32_t* a, uint32_t b0, uint32_t b1) {
    asm volatile(
        "mma.sync.aligned.m16n8k16.row.col.f32.f16.f16.f32 "
        "{%0,%1,%2,%3}, {%4,%5,%6,%7}, {%8,%9}, {%0,%1,%2,%3};"
        : "+f"(d[0]), "+f"(d[1]), "+f"(d[2]), "+f"(d[3])
        : "r"(a[0]), "r"(a[1]), "r"(a[2]), "r"(a[3]), "r"(b0), "r"(b1));
}

// fast device math (phase bounded to [-pi, pi] -> MUFU sin/cos accurate)
__device__ __forceinline__ float ftanh(float x) {
    float e;
    asm("ex2.approx.f32 %0, %1;" : "=f"(e) : "f"(x * 2.8853900817779268f)); // e^(2x)
    float r;
    asm("rcp.approx.f32 %0, %1;" : "=f"(r) : "f"(e + 1.0f));
    return fmaf(-2.0f, r, 1.0f);
}
__device__ __forceinline__ float fsin(float x) { float r; asm("sin.approx.f32 %0, %1;" : "=f"(r) : "f"(x)); return r; }
__device__ __forceinline__ float fcos(float x) { float r; asm("cos.approx.f32 %0, %1;" : "=f"(r) : "f"(x)); return r; }

// ---------------------------------------------------------------------------
// Scratch (device globals — allocation-free per harness rules)
// ---------------------------------------------------------------------------
__device__ float g_f0[(size_t)Mq * Dq];   // value
__device__ float g_f1[(size_t)Mq * Dq];   // kp_lin
__device__ float g_f2[(size_t)Mq * Dq];   // qp_lin
__device__ float g_f3[(size_t)Mq * Dq];   // retrieved
__device__ __align__(256) __half g_xh[(size_t)Mq * Dq];   // x fp16
__device__ __align__(256) __half g_ah[(size_t)Mq * Dq];   // ln fp16
__device__ __align__(256) __half g_wh[8 * (size_t)Dq * Dq];
// slots: 0=Wv64 1=Wo64 2=Wkp64 3=Wqp64 4=WkT64 5=WqT64 6=Ckp64 7=Cqp64
__device__ float g_zero[Dq];              // static zero-init
__device__ float g_bkp[Dq];               // combined kp bias
__device__ float g_bqp[Dq];               // combined qp bias

// ---------------------------------------------------------------------------
// fp32 -> fp16 convert (activations)
// ---------------------------------------------------------------------------
__global__ __launch_bounds__(256)
void convert_kernel(const float* __restrict__ in, __half* __restrict__ out)
{
    const size_t i4 = (size_t)blockIdx.x * blockDim.x + threadIdx.x;
    float4 v = *(const float4*)(in + i4 * 4);
    __half2 a = __floats2half2_rn(v.x, v.y);
    __half2 b = __floats2half2_rn(v.z, v.w);
    uint2 p;
    p.x = *(uint32_t*)&a;
    p.y = *(uint32_t*)&b;
    *(uint2*)(out + i4 * 4) = p;
}

// W*64 -> fp16
__global__ __launch_bounds__(256)
void convert_w64_kernel(const float* __restrict__ in, __half* __restrict__ out)
{
    const size_t i4 = (size_t)blockIdx.x * blockDim.x + threadIdx.x;
    float4 v = *(const float4*)(in + i4 * 4);
    __half2 a = __floats2half2_rn(v.x * 64.0f, v.y * 64.0f);
    __half2 b = __floats2half2_rn(v.z * 64.0f, v.w * 64.0f);
    uint2 p;
    p.x = *(uint32_t*)&a;
    p.y = *(uint32_t*)&b;
    *(uint2*)(out + i4 * 4) = p;
}

// Transposed W*64 -> fp16 (out[j,i] = in[i,j]*64), 32x32 smem tiles
__global__ __launch_bounds__(256)
void transpose_w64_kernel(const float* __restrict__ in, __half* __restrict__ out)
{
    __shared__ float tile[32][33];
    const int tx = threadIdx.x & 31;
    const int ty = threadIdx.x >> 5;       // 0..7
    const int x0 = blockIdx.x * 32;
    const int y0 = blockIdx.y * 32;
#pragma unroll
    for (int i = 0; i < 32; i += 8)
        tile[ty + i][tx] = in[(size_t)(y0 + ty + i) * Dq + x0 + tx];
    __syncthreads();
#pragma unroll
    for (int i = 0; i < 32; i += 8)
        out[(size_t)(x0 + ty + i) * Dq + y0 + tx] = __float2half_rn(tile[tx][ty + i] * 64.0f);
}

// out[i] = sum_k W[i,k]*v[k] + b2[i]   (fp32, exactish combined bias)
__global__ __launch_bounds__(256)
void matvec_bias_kernel(const float* __restrict__ W, const float* __restrict__ v,
                        const float* __restrict__ b2, float* __restrict__ out)
{
    const int row  = blockIdx.x * 8 + (threadIdx.x >> 5);
    const int lane = threadIdx.x & 31;
    const float* r = W + (size_t)row * Dq;
    float s = 0.0f;
#pragma unroll
    for (int k = lane * 4; k < Dq; k += 128) {
        float4 a = *(const float4*)(r + k);
        float4 x = *(const float4*)(v + k);
        s += a.x * x.x + a.y * x.y + a.z * x.z + a.w * x.w;
    }
#pragma unroll
    for (int o = 16; o > 0; o >>= 1) s += __shfl_xor_sync(0xFFFFFFFFu, s, o);
    if (lane == 0) out[row] = s + b2[row];
}

// ---------------------------------------------------------------------------
// fp16 single-product GEMM (NT): C = (A * W64) / 64 + bias (+resid)
// CTA 128x128, K-step 32, 4-stage cp.async, 8 warps (32x64 each), 2 CTAs/SM.
// ---------------------------------------------------------------------------
constexpr int TILE_B   = 10240;             // 128 rows * 80 B
constexpr int STAGE_B  = 2 * TILE_B;        // A | W
constexpr int SMEM_TOT = 4 * STAGE_B;       // 81920

__device__ __forceinline__ void load_stage(
    uint32_t sb_stage, int kb, int tid,
    const __half* __restrict__ A, const __half* __restrict__ W, int bm, int bn)
{
    const __half* srcs[2] = {A, W};
    const int rb[2] = {bm, bn};
#pragma unroll
    for (int t = 0; t < 2; t++) {
#pragma unroll
        for (int i = 0; i < 2; i++) {
            const int idx = i * 256 + tid;     // 0..511
            const int row = idx >> 2;
            const int ch  = idx & 3;
            const __half* g = srcs[t] + (((size_t)(rb[t] + row)) << 10) + kb * 32 + ch * 8;
            const uint32_t d = sb_stage + t * TILE_B + row * 80 + ch * 16;
            CP_ASYNC16(d, g);
        }
    }
}

template <bool OUT_FP16, bool RESID>
__global__ __launch_bounds__(256, 2)
void gemm_mma(const __half* __restrict__ A, const __half* __restrict__ W,
              const float* __restrict__ bias, const float* __restrict__ resid,
              float* __restrict__ Cf, __half* __restrict__ Ch)
{
    extern __shared__ __align__(128) char smem[];
    const uint32_t sb = smem_u32(smem);
    const int tid  = threadIdx.x;
    const int wid  = tid >> 5;
    const int lane = tid & 31;
    const int bm = blockIdx.y * 128;
    const int bn = blockIdx.x * 128;
    const int wm = (wid >> 1) * 32;
    const int wn = (wid & 1) * 64;

    float acc[2][8][4];
#pragma unroll
    for (int i = 0; i < 2; i++)
#pragma unroll
        for (int j = 0; j < 8; j++)
#pragma unroll
            for (int k = 0; k < 4; k++) acc[i][j][k] = 0.0f;

    load_stage(sb + 0 * STAGE_B, 0, tid, A, W, bm, bn); CP_COMMIT();
    load_stage(sb + 1 * STAGE_B, 1, tid, A, W, bm, bn); CP_COMMIT();
    load_stage(sb + 2 * STAGE_B, 2, tid, A, W, bm, bn); CP_COMMIT();

    const int sub = lane >> 3;
    const int rr  = lane & 7;

    for (int kb = 0; kb < 32; kb++) {
        CP_WAIT2();
        __syncthreads();
        if (kb + 3 < 32)
            load_stage(sb + ((kb + 3) & 3) * STAGE_B, kb + 3, tid, A, W, bm, bn);
        CP_COMMIT();

        const uint32_t st = sb + (kb & 3) * STAGE_B;
        const uint32_t sA = st;
        const uint32_t sB = st + TILE_B;

#pragma unroll
        for (int kk = 0; kk < 2; kk++) {
            const int chunk = kk * 2 + (sub >> 1);
            uint32_t fa[2][4], fb[4][4];
#pragma unroll
            for (int mt = 0; mt < 2; mt++) {
                const int row = wm + mt * 16 + (sub & 1) * 8 + rr;
                ldsm4(fa[mt], sA + row * 80 + chunk * 16);
            }
#pragma unroll
            for (int g = 0; g < 4; g++) {
                const int row = wn + g * 16 + (sub & 1) * 8 + rr;
                ldsm4(fb[g], sB + row * 80 + chunk * 16);
            }
#pragma unroll
            for (int mt = 0; mt < 2; mt++) {
#pragma unroll
                for (int g = 0; g < 4; g++) {
                    mma_f16(acc[mt][2 * g],     fa[mt], fb[g][0], fb[g][2]);
                    mma_f16(acc[mt][2 * g + 1], fa[mt], fb[g][1], fb[g][3]);
                }
            }
        }
    }

    const int qrow = lane >> 2;
    const int qcol = (lane & 3) * 2;
#pragma unroll
    for (int mt = 0; mt < 2; mt++) {
#pragma unroll
        for (int nt = 0; nt < 8; nt++) {
            const int col = bn + wn + nt * 8 + qcol;
            const float bz0 = __ldg(bias + col);
            const float bz1 = __ldg(bias + col + 1);
#pragma unroll
            for (int h = 0; h < 2; h++) {
                const int row = bm + wm + mt * 16 + h * 8 + qrow;
                float v0 = acc[mt][nt][2 * h + 0] * 0.015625f + bz0;
                float v1 = acc[mt][nt][2 * h + 1] * 0.015625f + bz1;
                const size_t go = ((size_t)row << 10) + col;
                if (RESID) {
                    float2 x2 = *(const float2*)(resid + go);
                    v0 += x2.x; v1 += x2.y;
                }
                if (OUT_FP16) {
                    __half2 hv = __floats2half2_rn(v0, v1);
                    *(uint32_t*)(Ch + go) = *(uint32_t*)&hv;
                } else {
                    float2 o; o.x = v0; o.y = v1;
                    *(float2*)(Cf + go) = o;
                }
            }
        }
    }
}

// ---------------------------------------------------------------------------
// Phasor kernel with MUFU fast math
// ---------------------------------------------------------------------------
__global__ void phasor_kernel(const float* __restrict__ kp_lin,
                              const float* __restrict__ qp_lin,
                              const float* __restrict__ val,
                              const float* __restrict__ phase_scale,
                              float* __restrict__ retrieved)
{
    const int idx = blockIdx.x * blockDim.x + threadIdx.x;
    const int d     = idx & (Dq - 1);
    const int chunk = (idx >> 10) & (NCHUNK - 1);
    const int b     = idx >> 16;
    const float ps  = phase_scale[d];
    size_t off = ((size_t)b * Sq + (size_t)chunk * CHUNKq) * Dq + d;

    float mr = 0.0f, mi = 0.0f;
#pragma unroll 4
    for (int s = 0; s < CHUNKq; s++) {
        const float kp = ftanh(kp_lin[off]) * ps;
        const float qp = ftanh(qp_lin[off]) * ps;
        const float v  = val[off];
        mr = fmaf(v, fcos(kp), mr);
        mi = fmaf(v, fsin(kp), mi);
        retrieved[off] = (mr * fcos(qp) + mi * fsin(qp)) * 0.03125f;
        off += Dq;
    }
}

// ---------------------------------------------------------------------------
// LayerNorm (1024) -> fp16 output
// ---------------------------------------------------------------------------
__global__ __launch_bounds__(256)
void layernorm_kernel(const float* __restrict__ in,
                      const float* __restrict__ g,
                      const float* __restrict__ b,
                      __half* __restrict__ outh)
{
    __shared__ float s_sum[8];
    __shared__ float s_sq[8];
    const int row = blockIdx.x;
    const int tid = threadIdx.x;
    const float* rin = in + (size_t)row * Dq;

    float4 x4 = *(const float4*)&rin[tid * 4];
    float s  = x4.x + x4.y + x4.z + x4.w;
    float sq = x4.x * x4.x + x4.y * x4.y + x4.z * x4.z + x4.w * x4.w;
#pragma unroll
    for (int o = 16; o > 0; o >>= 1) {
        s  += __shfl_xor_sync(0xFFFFFFFFu, s, o);
        sq += __shfl_xor_sync(0xFFFFFFFFu, sq, o);
    }
    const int warp = tid >> 5;
    if ((tid & 31) == 0) { s_sum[warp] = s; s_sq[warp] = sq; }
    __syncthreads();
    if (warp == 0) {
        s  = s_sum[tid & 7];
        sq = s_sq[tid & 7];
#pragma unroll
        for (int o = 4; o > 0; o >>= 1) {
            s  += __shfl_xor_sync(0xFFFFFFFFu, s, o);
            sq += __shfl_xor_sync(0xFFFFFFFFu, sq, o);
        }
        if (tid == 0) { s_sum[0] = s; s_sq[0] = sq; }
    }
    __syncthreads();
    const float mu   = s_sum[0] * (1.0f / Dq);
    const float var  = s_sq[0] * (1.0f / Dq) - mu * mu;
    const float rstd = rsqrtf(var + 1e-5f);

    float4 g4 = *(const float4*)&g[tid * 4];
    float4 b4 = *(const float4*)&b[tid * 4];
    __half2 h0 = __floats2half2_rn((x4.x - mu) * rstd * g4.x + b4.x,
                                   (x4.y - mu) * rstd * g4.y + b4.y);
    __half2 h1 = __floats2half2_rn((x4.z - mu) * rstd * g4.z + b4.z,
                                   (x4.w - mu) * rstd * g4.w + b4.w);
    uint2 p;
    p.x = *(uint32_t*)&h0;
    p.y = *(uint32_t*)&h1;
    *(uint2*)(outh + (size_t)row * Dq + tid * 4) = p;
}

// ---------------------------------------------------------------------------
// Launch
// ---------------------------------------------------------------------------
extern "C" void kernel_launch(void* const* d_in, const int* in_sizes, int n_in,
                              void* d_out, int out_size)
{
    (void)in_sizes; (void)n_in; (void)out_size;
    const float* x   = (const float*)d_in[0];
    const float* Wk  = (const float*)d_in[1];
    const float* bk  = (const float*)d_in[2];
    const float* Wv  = (const float*)d_in[3];
    const float* bv  = (const float*)d_in[4];
    const float* Wq  = (const float*)d_in[5];
    const float* bq  = (const float*)d_in[6];
    const float* Wkp = (const float*)d_in[7];
    const float* bkp = (const float*)d_in[8];
    const float* Wqp = (const float*)d_in[9];
    const float* bqp = (const float*)d_in[10];
    const float* ps  = (const float*)d_in[11];
    const float* lng = (const float*)d_in[12];
    const float* lnb = (const float*)d_in[13];
    const float* Wo  = (const float*)d_in[14];
    const float* bo  = (const float*)d_in[15];
    float* out = (float*)d_out;

    float *f0, *f1, *f2, *f3, *zero, *bkpc, *bqpc;
    __half *xh, *ah, *wh;
    cudaGetSymbolAddress((void**)&f0, g_f0);
    cudaGetSymbolAddress((void**)&f1, g_f1);
    cudaGetSymbolAddress((void**)&f2, g_f2);
    cudaGetSymbolAddress((void**)&f3, g_f3);
    cudaGetSymbolAddress((void**)&xh, g_xh);
    cudaGetSymbolAddress((void**)&ah, g_ah);
    cudaGetSymbolAddress((void**)&wh, g_wh);
    cudaGetSymbolAddress((void**)&zero, g_zero);
    cudaGetSymbolAddress((void**)&bkpc, g_bkp);
    cudaGetSymbolAddress((void**)&bqpc, g_bqp);

    cudaFuncSetAttribute(gemm_mma<false, false>, cudaFuncAttributeMaxDynamicSharedMemorySize, SMEM_TOT);
    cudaFuncSetAttribute(gemm_mma<true, false>,  cudaFuncAttributeMaxDynamicSharedMemorySize, SMEM_TOT);
    cudaFuncSetAttribute(gemm_mma<false, true>,  cudaFuncAttributeMaxDynamicSharedMemorySize, SMEM_TOT);

    const size_t WN = (size_t)Dq * Dq;
    __half* whV  = wh + 0 * WN;
    __half* whO  = wh + 1 * WN;
    __half* whKP = wh + 2 * WN;
    __half* whQP = wh + 3 * WN;
    __half* whKT = wh + 4 * WN;
    __half* whQT = wh + 5 * WN;
    __half* whCK = wh + 6 * WN;   // combined kp weight (x64)
    __half* whCQ = wh + 7 * WN;   // combined qp weight (x64)

    // Prep: converts / transposes / combined biases
    convert_kernel<<<(Mq * Dq) / 1024, 256>>>(x, xh);
    convert_w64_kernel<<<WN / 1024, 256>>>(Wv,  whV);
    convert_w64_kernel<<<WN / 1024, 256>>>(Wo,  whO);
    convert_w64_kernel<<<WN / 1024, 256>>>(Wkp, whKP);
    convert_w64_kernel<<<WN / 1024, 256>>>(Wqp, whQP);
    transpose_w64_kernel<<<dim3(32, 32), 256>>>(Wk, whKT);
    transpose_w64_kernel<<<dim3(32, 32), 256>>>(Wq, whQT);
    matvec_bias_kernel<<<Dq / 8, 256>>>(Wkp, bk, bkp, bkpc);
    matvec_bias_kernel<<<Dq / 8, 256>>>(Wqp, bq, bqp, bqpc);

    // Combine GEMMs: Ckp = Wkp @ Wk (both x64 -> acc/64 = 64*C in fp16)
    const dim3 gridW(Dq / 128, Dq / 128);   // (8, 8)
    const dim3 block(256);
    gemm_mma<true, false><<<gridW, block, SMEM_TOT>>>(whKP, whKT, zero, nullptr, nullptr, whCK);
    gemm_mma<true, false><<<gridW, block, SMEM_TOT>>>(whQP, whQT, zero, nullptr, nullptr, whCQ);

    // Big GEMMs
    const dim3 grid(Dq / 128, Mq / 128);    // (8, 128)
    // value -> f0
    gemm_mma<false, false><<<grid, block, SMEM_TOT>>>(xh, whV, bv, nullptr, f0, nullptr);
    // kp_lin = x @ Ckp^T + bkp' -> f1
    gemm_mma<false, false><<<grid, block, SMEM_TOT>>>(xh, whCK, bkpc, nullptr, f1, nullptr);
    // qp_lin = x @ Cqp^T + bqp' -> f2
    gemm_mma<false, false><<<grid, block, SMEM_TOT>>>(xh, whCQ, bqpc, nullptr, f2, nullptr);
    // phasor: (kp=f1, qp=f2, val=f0) -> f3
    phasor_kernel<<<(Bq * NCHUNK * Dq) / 256, 256>>>(f1, f2, f0, ps, f3);
    // layernorm f3 -> fp16 (ah)
    layernorm_kernel<<<Mq, 256>>>(f3, lng, lnb, ah);
    // out = x + ln @ Wo + bo
    gemm_mma<false, true><<<grid, block, SMEM_TOT>>>(ah, whO, bo, x, out, nullptr);
}

// round 7
// speedup vs baseline: 8.1978x; 1.0262x over previous
#include <cuda_runtime.h>
#include <cuda_fp16.h>
#include <math.h>
#include <stdint.h>

// Problem constants
#define Bq 4
#define Sq 4096
#define Dq 1024
#define Mq (Bq * Sq)          // 16384 rows
#define CHUNKq 64
#define NCHUNK (Sq / CHUNKq)  // 64

// ---------------------------------------------------------------------------
// PTX helpers (compute_103-safe)
// ---------------------------------------------------------------------------
__device__ __forceinline__ uint32_t smem_u32(const void* p) {
    uint32_t a;
    asm("{ .reg .u64 t; cvta.to.shared.u64 t, %1; cvt.u32.u64 %0, t; }" : "=r"(a) : "l"(p));
    return a;
}
#define CP_ASYNC16(dst, src) \
    asm volatile("cp.async.cg.shared.global [%0], [%1], 16;" :: "r"(dst), "l"(src))
#define CP_COMMIT() asm volatile("cp.async.commit_group;" ::: "memory")
#define CP_WAIT2()  asm volatile("cp.async.wait_group 2;" ::: "memory")

__device__ __forceinline__ void ldsm4(uint32_t* r, uint32_t addr) {
    asm volatile("ldmatrix.sync.aligned.m8n8.x4.shared.b16 {%0,%1,%2,%3}, [%4];"
                 : "=r"(r[0]), "=r"(r[1]), "=r"(r[2]), "=r"(r[3]) : "r"(addr));
}
__device__ __forceinline__ void mma_f16(float* d, const uint32_t* a, uint32_t b0, uint32_t b1) {
    asm volatile(
        "mma.sync.aligned.m16n8k16.row.col.f32.f16.f16.f32 "
        "{%0,%1,%2,%3}, {%4,%5,%6,%7}, {%8,%9}, {%0,%1,%2,%3};"
        : "+f"(d[0]), "+f"(d[1]), "+f"(d[2]), "+f"(d[3])
        : "r"(a[0]), "r"(a[1]), "r"(a[2]), "r"(a[3]), "r"(b0), "r"(b1));
}

// fast device math (phase bounded to [-pi, pi] -> MUFU sin/cos accurate)
__device__ __forceinline__ float ftanh(float x) {
    float e;
    asm("ex2.approx.f32 %0, %1;" : "=f"(e) : "f"(x * 2.8853900817779268f)); // e^(2x)
    float r;
    asm("rcp.approx.f32 %0, %1;" : "=f"(r) : "f"(e + 1.0f));
    return fmaf(-2.0f, r, 1.0f);
}
__device__ __forceinline__ float fsin(float x) { float r; asm("sin.approx.f32 %0, %1;" : "=f"(r) : "f"(x)); return r; }
__device__ __forceinline__ float fcos(float x) { float r; asm("cos.approx.f32 %0, %1;" : "=f"(r) : "f"(x)); return r; }

// ---------------------------------------------------------------------------
// Scratch (device globals — allocation-free per harness rules)
// ---------------------------------------------------------------------------
__device__ __align__(256) __half g_xh[(size_t)Mq * Dq];   // x fp16
__device__ __align__(256) __half g_vh[(size_t)Mq * Dq];   // value fp16
__device__ __align__(256) __half g_kh[(size_t)Mq * Dq];   // kp_lin fp16
__device__ __align__(256) __half g_qh[(size_t)Mq * Dq];   // qp_lin fp16
__device__ __align__(256) __half g_ah[(size_t)Mq * Dq];   // ln output fp16
__device__ __align__(256) __half g_wh[8 * (size_t)Dq * Dq];
// slots: 0=Wv64 1=Wo64 2=Wkp64 3=Wqp64 4=WkT64 5=WqT64 6=Ckp64 7=Cqp64
__device__ float g_zero[Dq];              // static zero-init
__device__ float g_bkp[Dq];               // combined kp bias
__device__ float g_bqp[Dq];               // combined qp bias

// ---------------------------------------------------------------------------
// fp32 -> fp16 convert (activations)
// ---------------------------------------------------------------------------
__global__ __launch_bounds__(256)
void convert_kernel(const float* __restrict__ in, __half* __restrict__ out)
{
    const size_t i4 = (size_t)blockIdx.x * blockDim.x + threadIdx.x;
    float4 v = *(const float4*)(in + i4 * 4);
    __half2 a = __floats2half2_rn(v.x, v.y);
    __half2 b = __floats2half2_rn(v.z, v.w);
    uint2 p;
    p.x = *(uint32_t*)&a;
    p.y = *(uint32_t*)&b;
    *(uint2*)(out + i4 * 4) = p;
}

// 4 weights * 64 -> fp16, one launch (blockIdx.y selects tensor)
__global__ __launch_bounds__(256)
void convert_w64_quad_kernel(const float* __restrict__ w0, const float* __restrict__ w1,
                             const float* __restrict__ w2, const float* __restrict__ w3,
                             __half* __restrict__ o0, __half* __restrict__ o1,
                             __half* __restrict__ o2, __half* __restrict__ o3)
{
    const float* in;
    __half* out;
    switch (blockIdx.y) {
        case 0: in = w0; out = o0; break;
        case 1: in = w1; out = o1; break;
        case 2: in = w2; out = o2; break;
        default: in = w3; out = o3; break;
    }
    const size_t i4 = (size_t)blockIdx.x * blockDim.x + threadIdx.x;
    float4 v = *(const float4*)(in + i4 * 4);
    __half2 a = __floats2half2_rn(v.x * 64.0f, v.y * 64.0f);
    __half2 b = __floats2half2_rn(v.z * 64.0f, v.w * 64.0f);
    uint2 p;
    p.x = *(uint32_t*)&a;
    p.y = *(uint32_t*)&b;
    *(uint2*)(out + i4 * 4) = p;
}

// Transposed W*64 -> fp16, dual (blockIdx.z selects tensor)
__global__ __launch_bounds__(256)
void transpose_w64_dual_kernel(const float* __restrict__ in0, __half* __restrict__ out0,
                               const float* __restrict__ in1, __half* __restrict__ out1)
{
    __shared__ float tile[32][33];
    const float* in = blockIdx.z ? in1 : in0;
    __half* out = blockIdx.z ? out1 : out0;
    const int tx = threadIdx.x & 31;
    const int ty = threadIdx.x >> 5;       // 0..7
    const int x0 = blockIdx.x * 32;
    const int y0 = blockIdx.y * 32;
#pragma unroll
    for (int i = 0; i < 32; i += 8)
        tile[ty + i][tx] = in[(size_t)(y0 + ty + i) * Dq + x0 + tx];
    __syncthreads();
#pragma unroll
    for (int i = 0; i < 32; i += 8)
        out[(size_t)(x0 + ty + i) * Dq + y0 + tx] = __float2half_rn(tile[tx][ty + i] * 64.0f);
}

// out[i] = sum_k W[i,k]*v[k] + b2[i], dual (blockIdx.y selects problem)
__global__ __launch_bounds__(256)
void matvec_bias_dual_kernel(const float* __restrict__ W0, const float* __restrict__ v0,
                             const float* __restrict__ b20, float* __restrict__ out0,
                             const float* __restrict__ W1, const float* __restrict__ v1,
                             const float* __restrict__ b21, float* __restrict__ out1)
{
    const float* W = blockIdx.y ? W1 : W0;
    const float* v = blockIdx.y ? v1 : v0;
    const float* b2 = blockIdx.y ? b21 : b20;
    float* out = blockIdx.y ? out1 : out0;
    const int row  = blockIdx.x * 8 + (threadIdx.x >> 5);
    const int lane = threadIdx.x & 31;
    const float* r = W + (size_t)row * Dq;
    float s = 0.0f;
#pragma unroll
    for (int k = lane * 4; k < Dq; k += 128) {
        float4 a = *(const float4*)(r + k);
        float4 x = *(const float4*)(v + k);
        s += a.x * x.x + a.y * x.y + a.z * x.z + a.w * x.w;
    }
#pragma unroll
    for (int o = 16; o > 0; o >>= 1) s += __shfl_xor_sync(0xFFFFFFFFu, s, o);
    if (lane == 0) out[row] = s + b2[row];
}

// ---------------------------------------------------------------------------
// fp16 single-product GEMM body (NT): C = (A * W64) / 64 + bias (+resid)
// CTA 128x128, K-step 32, 4-stage cp.async, 8 warps (32x64 each), 2 CTAs/SM.
// ---------------------------------------------------------------------------
constexpr int TILE_B   = 10240;             // 128 rows * 80 B
constexpr int STAGE_B  = 2 * TILE_B;        // A | W
constexpr int SMEM_TOT = 4 * STAGE_B;       // 81920

__device__ __forceinline__ void load_stage(
    uint32_t sb_stage, int kb, int tid,
    const __half* __restrict__ A, const __half* __restrict__ W, int bm, int bn)
{
    const __half* srcs[2] = {A, W};
    const int rb[2] = {bm, bn};
#pragma unroll
    for (int t = 0; t < 2; t++) {
#pragma unroll
        for (int i = 0; i < 2; i++) {
            const int idx = i * 256 + tid;     // 0..511
            const int row = idx >> 2;
            const int ch  = idx & 3;
            const __half* g = srcs[t] + (((size_t)(rb[t] + row)) << 10) + kb * 32 + ch * 8;
            const uint32_t d = sb_stage + t * TILE_B + row * 80 + ch * 16;
            CP_ASYNC16(d, g);
        }
    }
}

template <bool OUT_FP16, bool RESID>
__device__ __forceinline__ void gemm_body(
    const __half* __restrict__ A, const __half* __restrict__ W,
    const float* __restrict__ bias, const float* __restrict__ resid,
    float* __restrict__ Cf, __half* __restrict__ Ch)
{
    extern __shared__ __align__(128) char smem[];
    const uint32_t sb = smem_u32(smem);
    const int tid  = threadIdx.x;
    const int wid  = tid >> 5;
    const int lane = tid & 31;
    const int bm = blockIdx.y * 128;
    const int bn = blockIdx.x * 128;
    const int wm = (wid >> 1) * 32;
    const int wn = (wid & 1) * 64;

    float acc[2][8][4];
#pragma unroll
    for (int i = 0; i < 2; i++)
#pragma unroll
        for (int j = 0; j < 8; j++)
#pragma unroll
            for (int k = 0; k < 4; k++) acc[i][j][k] = 0.0f;

    load_stage(sb + 0 * STAGE_B, 0, tid, A, W, bm, bn); CP_COMMIT();
    load_stage(sb + 1 * STAGE_B, 1, tid, A, W, bm, bn); CP_COMMIT();
    load_stage(sb + 2 * STAGE_B, 2, tid, A, W, bm, bn); CP_COMMIT();

    const int sub = lane >> 3;
    const int rr  = lane & 7;

    for (int kb = 0; kb < 32; kb++) {
        CP_WAIT2();
        __syncthreads();
        if (kb + 3 < 32)
            load_stage(sb + ((kb + 3) & 3) * STAGE_B, kb + 3, tid, A, W, bm, bn);
        CP_COMMIT();

        const uint32_t st = sb + (kb & 3) * STAGE_B;
        const uint32_t sA = st;
        const uint32_t sB = st + TILE_B;

#pragma unroll
        for (int kk = 0; kk < 2; kk++) {
            const int chunk = kk * 2 + (sub >> 1);
            uint32_t fa[2][4], fb[4][4];
#pragma unroll
            for (int mt = 0; mt < 2; mt++) {
                const int row = wm + mt * 16 + (sub & 1) * 8 + rr;
                ldsm4(fa[mt], sA + row * 80 + chunk * 16);
            }
#pragma unroll
            for (int g = 0; g < 4; g++) {
                const int row = wn + g * 16 + (sub & 1) * 8 + rr;
                ldsm4(fb[g], sB + row * 80 + chunk * 16);
            }
#pragma unroll
            for (int mt = 0; mt < 2; mt++) {
#pragma unroll
                for (int g = 0; g < 4; g++) {
                    mma_f16(acc[mt][2 * g],     fa[mt], fb[g][0], fb[g][2]);
                    mma_f16(acc[mt][2 * g + 1], fa[mt], fb[g][1], fb[g][3]);
                }
            }
        }
    }

    const int qrow = lane >> 2;
    const int qcol = (lane & 3) * 2;
#pragma unroll
    for (int mt = 0; mt < 2; mt++) {
#pragma unroll
        for (int nt = 0; nt < 8; nt++) {
            const int col = bn + wn + nt * 8 + qcol;
            const float bz0 = __ldg(bias + col);
            const float bz1 = __ldg(bias + col + 1);
#pragma unroll
            for (int h = 0; h < 2; h++) {
                const int row = bm + wm + mt * 16 + h * 8 + qrow;
                float v0 = acc[mt][nt][2 * h + 0] * 0.015625f + bz0;
                float v1 = acc[mt][nt][2 * h + 1] * 0.015625f + bz1;
                const size_t go = ((size_t)row << 10) + col;
                if (RESID) {
                    float2 x2 = *(const float2*)(resid + go);
                    v0 += x2.x; v1 += x2.y;
                }
                if (OUT_FP16) {
                    __half2 hv = __floats2half2_rn(v0, v1);
                    *(uint32_t*)(Ch + go) = *(uint32_t*)&hv;
                } else {
                    float2 o; o.x = v0; o.y = v1;
                    *(float2*)(Cf + go) = o;
                }
            }
        }
    }
}

template <bool OUT_FP16, bool RESID>
__global__ __launch_bounds__(256, 2)
void gemm_mma(const __half* __restrict__ A, const __half* __restrict__ W,
              const float* __restrict__ bias, const float* __restrict__ resid,
              float* __restrict__ Cf, __half* __restrict__ Ch)
{
    gemm_body<OUT_FP16, RESID>(A, W, bias, resid, Cf, Ch);
}

// Two independent fp16-out GEMMs in one launch (blockIdx.z selects)
__global__ __launch_bounds__(256, 2)
void gemm_dual(const __half* __restrict__ A0, const __half* __restrict__ W0, __half* __restrict__ C0,
               const __half* __restrict__ A1, const __half* __restrict__ W1, __half* __restrict__ C1,
               const float* __restrict__ zerob)
{
    if (blockIdx.z == 0)
        gemm_body<true, false>(A0, W0, zerob, nullptr, nullptr, C0);
    else
        gemm_body<true, false>(A1, W1, zerob, nullptr, nullptr, C1);
}

// ---------------------------------------------------------------------------
// Fused phasor + LayerNorm: one block per chunk (64 s-rows x 1024 d).
// 256 threads x 4 d each. Cumsum in registers; per-s block reduce for LN.
// Inputs fp16, output fp16 (feeds the out-projection GEMM).
// ---------------------------------------------------------------------------
__global__ __launch_bounds__(256)
void lnphasor_kernel(const __half* __restrict__ kp16, const __half* __restrict__ qp16,
                     const __half* __restrict__ v16,  const float* __restrict__ ps,
                     const float* __restrict__ lng,   const float* __restrict__ lnb,
                     __half* __restrict__ outh)
{
    __shared__ float sred[2][2][8];
    __shared__ float smu[2][2];
    const int tid  = threadIdx.x;
    const int warp = tid >> 5;
    const int lane = tid & 31;
    const int d0 = tid * 4;

    const float4 ps4 = *(const float4*)(ps + d0);
    const float4 g4  = *(const float4*)(lng + d0);
    const float4 b4  = *(const float4*)(lnb + d0);
    const float psv[4] = {ps4.x, ps4.y, ps4.z, ps4.w};
    const float gv[4]  = {g4.x, g4.y, g4.z, g4.w};
    const float bv[4]  = {b4.x, b4.y, b4.z, b4.w};

    float mr[4] = {0, 0, 0, 0}, mi[4] = {0, 0, 0, 0};

    for (int s = 0; s < CHUNKq; s++) {
        const size_t off = (((size_t)blockIdx.x * CHUNKq + s) << 10) + d0;
        uint2 kpu = *(const uint2*)(kp16 + off);
        uint2 qpu = *(const uint2*)(qp16 + off);
        uint2 vu  = *(const uint2*)(v16 + off);
        float2 kpa = __half22float2(*(__half2*)&kpu.x);
        float2 kpb = __half22float2(*(__half2*)&kpu.y);
        float2 qpa = __half22float2(*(__half2*)&qpu.x);
        float2 qpb = __half22float2(*(__half2*)&qpu.y);
        float2 va  = __half22float2(*(__half2*)&vu.x);
        float2 vb  = __half22float2(*(__half2*)&vu.y);
        const float kpf[4] = {kpa.x, kpa.y, kpb.x, kpb.y};
        const float qpf[4] = {qpa.x, qpa.y, qpb.x, qpb.y};
        const float vf[4]  = {va.x, va.y, vb.x, vb.y};

        float r[4];
        float s1 = 0.0f, s2 = 0.0f;
#pragma unroll
        for (int j = 0; j < 4; j++) {
            const float kp = ftanh(kpf[j]) * psv[j];
            const float qp = ftanh(qpf[j]) * psv[j];
            mr[j] = fmaf(vf[j], fcos(kp), mr[j]);
            mi[j] = fmaf(vf[j], fsin(kp), mi[j]);
            r[j] = (mr[j] * fcos(qp) + mi[j] * fsin(qp)) * 0.03125f;
            s1 += r[j];
            s2 = fmaf(r[j], r[j], s2);
        }
        // block reduce (1024 values)
#pragma unroll
        for (int o = 16; o > 0; o >>= 1) {
            s1 += __shfl_xor_sync(0xFFFFFFFFu, s1, o);
            s2 += __shfl_xor_sync(0xFFFFFFFFu, s2, o);
        }
        const int buf = s & 1;
        if (lane == 0) { sred[buf][0][warp] = s1; sred[buf][1][warp] = s2; }
        __syncthreads();
        if (warp == 0) {
            float a = sred[buf][0][lane & 7];
            float c = sred[buf][1][lane & 7];
#pragma unroll
            for (int o = 4; o > 0; o >>= 1) {
                a += __shfl_xor_sync(0xFFFFFFFFu, a, o);
                c += __shfl_xor_sync(0xFFFFFFFFu, c, o);
            }
            if (lane == 0) { smu[buf][0] = a; smu[buf][1] = c; }
        }
        __syncthreads();
        const float mu   = smu[buf][0] * (1.0f / Dq);
        const float var  = smu[buf][1] * (1.0f / Dq) - mu * mu;
        const float rstd = rsqrtf(var + 1e-5f);

        __half2 h0 = __floats2half2_rn((r[0] - mu) * rstd * gv[0] + bv[0],
                                       (r[1] - mu) * rstd * gv[1] + bv[1]);
        __half2 h1 = __floats2half2_rn((r[2] - mu) * rstd * gv[2] + bv[2],
                                       (r[3] - mu) * rstd * gv[3] + bv[3]);
        uint2 p;
        p.x = *(uint32_t*)&h0;
        p.y = *(uint32_t*)&h1;
        *(uint2*)(outh + off) = p;
    }
}

// ---------------------------------------------------------------------------
// Launch
// ---------------------------------------------------------------------------
extern "C" void kernel_launch(void* const* d_in, const int* in_sizes, int n_in,
                              void* d_out, int out_size)
{
    (void)in_sizes; (void)n_in; (void)out_size;
    const float* x   = (const float*)d_in[0];
    const float* Wk  = (const float*)d_in[1];
    const float* bk  = (const float*)d_in[2];
    const float* Wv  = (const float*)d_in[3];
    const float* bv  = (const float*)d_in[4];
    const float* Wq  = (const float*)d_in[5];
    const float* bq  = (const float*)d_in[6];
    const float* Wkp = (const float*)d_in[7];
    const float* bkp = (const float*)d_in[8];
    const float* Wqp = (const float*)d_in[9];
    const float* bqp = (const float*)d_in[10];
    const float* ps  = (const float*)d_in[11];
    const float* lng = (const float*)d_in[12];
    const float* lnb = (const float*)d_in[13];
    const float* Wo  = (const float*)d_in[14];
    const float* bo  = (const float*)d_in[15];
    float* out = (float*)d_out;

    float *zero, *bkpc, *bqpc;
    __half *xh, *vh, *kh, *qh, *ah, *wh;
    cudaGetSymbolAddress((void**)&xh, g_xh);
    cudaGetSymbolAddress((void**)&vh, g_vh);
    cudaGetSymbolAddress((void**)&kh, g_kh);
    cudaGetSymbolAddress((void**)&qh, g_qh);
    cudaGetSymbolAddress((void**)&ah, g_ah);
    cudaGetSymbolAddress((void**)&wh, g_wh);
    cudaGetSymbolAddress((void**)&zero, g_zero);
    cudaGetSymbolAddress((void**)&bkpc, g_bkp);
    cudaGetSymbolAddress((void**)&bqpc, g_bqp);

    cudaFuncSetAttribute(gemm_mma<true, false>,  cudaFuncAttributeMaxDynamicSharedMemorySize, SMEM_TOT);
    cudaFuncSetAttribute(gemm_mma<false, true>,  cudaFuncAttributeMaxDynamicSharedMemorySize, SMEM_TOT);
    cudaFuncSetAttribute(gemm_dual,              cudaFuncAttributeMaxDynamicSharedMemorySize, SMEM_TOT);

    const size_t WN = (size_t)Dq * Dq;
    __half* whV  = wh + 0 * WN;
    __half* whO  = wh + 1 * WN;
    __half* whKP = wh + 2 * WN;
    __half* whQP = wh + 3 * WN;
    __half* whKT = wh + 4 * WN;
    __half* whQT = wh + 5 * WN;
    __half* whCK = wh + 6 * WN;   // combined kp weight (x64)
    __half* whCQ = wh + 7 * WN;   // combined qp weight (x64)

    // Prep (merged launches)
    convert_kernel<<<(Mq * Dq) / 1024, 256>>>(x, xh);
    convert_w64_quad_kernel<<<dim3(WN / 1024, 4), 256>>>(Wv, Wo, Wkp, Wqp, whV, whO, whKP, whQP);
    transpose_w64_dual_kernel<<<dim3(32, 32, 2), 256>>>(Wk, whKT, Wq, whQT);
    matvec_bias_dual_kernel<<<dim3(Dq / 8, 2), 256>>>(Wkp, bk, bkp, bkpc, Wqp, bq, bqp, bqpc);

    // Combined-weight GEMMs, one launch (128 CTAs concurrent)
    const dim3 block(256);
    gemm_dual<<<dim3(Dq / 128, Dq / 128, 2), block, SMEM_TOT>>>(
        whKP, whKT, whCK, whQP, whQT, whCQ, zero);

    // Big GEMMs (fp16 outputs for the phasor inputs)
    const dim3 grid(Dq / 128, Mq / 128);    // (8, 128)
    gemm_mma<true, false><<<grid, block, SMEM_TOT>>>(xh, whV,  bv,   nullptr, nullptr, vh);
    gemm_mma<true, false><<<grid, block, SMEM_TOT>>>(xh, whCK, bkpc, nullptr, nullptr, kh);
    gemm_mma<true, false><<<grid, block, SMEM_TOT>>>(xh, whCQ, bqpc, nullptr, nullptr, qh);

    // Fused phasor + layernorm -> ah (fp16)
    lnphasor_kernel<<<Bq * NCHUNK, 256>>>(kh, qh, vh, ps, lng, lnb, ah);

    // out = x + ln @ Wo + bo
    gemm_mma<false, true><<<grid, block, SMEM_TOT>>>(ah, whO, bo, x, out, nullptr);
}

// round 8
// speedup vs baseline: 8.6759x; 1.0583x over previous
#include <cuda_runtime.h>
#include <cuda_fp16.h>
#include <math.h>
#include <stdint.h>

// Problem constants
#define Bq 4
#define Sq 4096
#define Dq 1024
#define Mq (Bq * Sq)          // 16384 rows
#define CHUNKq 64
#define NCHUNK (Sq / CHUNKq)  // 64

// ---------------------------------------------------------------------------
// PTX helpers (compute_103-safe)
// ---------------------------------------------------------------------------
__device__ __forceinline__ uint32_t smem_u32(const void* p) {
    uint32_t a;
    asm("{ .reg .u64 t; cvta.to.shared.u64 t, %1; cvt.u32.u64 %0, t; }" : "=r"(a) : "l"(p));
    return a;
}
#define CP_ASYNC16(dst, src) \
    asm volatile("cp.async.cg.shared.global [%0], [%1], 16;" :: "r"(dst), "l"(src))
#define CP_COMMIT() asm volatile("cp.async.commit_group;" ::: "memory")
#define CP_WAIT2()  asm volatile("cp.async.wait_group 2;" ::: "memory")

__device__ __forceinline__ void ldsm4(uint32_t* r, uint32_t addr) {
    asm volatile("ldmatrix.sync.aligned.m8n8.x4.shared.b16 {%0,%1,%2,%3}, [%4];"
                 : "=r"(r[0]), "=r"(r[1]), "=r"(r[2]), "=r"(r[3]) : "r"(addr));
}
__device__ __forceinline__ void mma_f16(float* d, const uint32_t* a, uint32_t b0, uint32_t b1) {
    asm volatile(
        "mma.sync.aligned.m16n8k16.row.col.f32.f16.f16.f32 "
        "{%0,%1,%2,%3}, {%4,%5,%6,%7}, {%8,%9}, {%0,%1,%2,%3};"
        : "+f"(d[0]), "+f"(d[1]), "+f"(d[2]), "+f"(d[3])
        : "r"(a[0]), "r"(a[1]), "r"(a[2]), "r"(a[3]), "r"(b0), "r"(b1));
}

// fast device math (phase bounded to [-pi, pi] -> MUFU sin/cos accurate)
__device__ __forceinline__ float ftanh(float x) {
    float e;
    asm("ex2.approx.f32 %0, %1;" : "=f"(e) : "f"(x * 2.8853900817779268f)); // e^(2x)
    float r;
    asm("rcp.approx.f32 %0, %1;" : "=f"(r) : "f"(e + 1.0f));
    return fmaf(-2.0f, r, 1.0f);
}
__device__ __forceinline__ float fsin(float x) { float r; asm("sin.approx.f32 %0, %1;" : "=f"(r) : "f"(x)); return r; }
__device__ __forceinline__ float fcos(float x) { float r; asm("cos.approx.f32 %0, %1;" : "=f"(r) : "f"(x)); return r; }

// ---------------------------------------------------------------------------
// Scratch (device globals — allocation-free per harness rules)
// ---------------------------------------------------------------------------
__device__ __align__(256) __half g_xh[(size_t)Mq * Dq];   // x fp16
__device__ __align__(256) __half g_vh[(size_t)Mq * Dq];   // value fp16
__device__ __align__(256) __half g_kh[(size_t)Mq * Dq];   // kp_lin fp16
__device__ __align__(256) __half g_qh[(size_t)Mq * Dq];   // qp_lin fp16
__device__ __align__(256) __half g_ah[(size_t)Mq * Dq];   // ln output fp16
__device__ __align__(256) __half g_wh[8 * (size_t)Dq * Dq];
// slots: 0=Wv64 1=Wo64 2=Wkp64 3=Wqp64 4=WkT64 5=WqT64 6=Ckp64 7=Cqp64
__device__ float g_zero[Dq];              // static zero-init
__device__ float g_bkp[Dq];               // combined kp bias
__device__ float g_bqp[Dq];               // combined qp bias

// ---------------------------------------------------------------------------
// fp32 -> fp16 convert (activations)
// ---------------------------------------------------------------------------
__global__ __launch_bounds__(256)
void convert_kernel(const float* __restrict__ in, __half* __restrict__ out)
{
    const size_t i4 = (size_t)blockIdx.x * blockDim.x + threadIdx.x;
    float4 v = *(const float4*)(in + i4 * 4);
    __half2 a = __floats2half2_rn(v.x, v.y);
    __half2 b = __floats2half2_rn(v.z, v.w);
    uint2 p;
    p.x = *(uint32_t*)&a;
    p.y = *(uint32_t*)&b;
    *(uint2*)(out + i4 * 4) = p;
}

// 4 weights * 64 -> fp16, one launch (blockIdx.y selects tensor)
__global__ __launch_bounds__(256)
void convert_w64_quad_kernel(const float* __restrict__ w0, const float* __restrict__ w1,
                             const float* __restrict__ w2, const float* __restrict__ w3,
                             __half* __restrict__ o0, __half* __restrict__ o1,
                             __half* __restrict__ o2, __half* __restrict__ o3)
{
    const float* in;
    __half* out;
    switch (blockIdx.y) {
        case 0: in = w0; out = o0; break;
        case 1: in = w1; out = o1; break;
        case 2: in = w2; out = o2; break;
        default: in = w3; out = o3; break;
    }
    const size_t i4 = (size_t)blockIdx.x * blockDim.x + threadIdx.x;
    float4 v = *(const float4*)(in + i4 * 4);
    __half2 a = __floats2half2_rn(v.x * 64.0f, v.y * 64.0f);
    __half2 b = __floats2half2_rn(v.z * 64.0f, v.w * 64.0f);
    uint2 p;
    p.x = *(uint32_t*)&a;
    p.y = *(uint32_t*)&b;
    *(uint2*)(out + i4 * 4) = p;
}

// Transposed W*64 -> fp16, dual (blockIdx.z selects tensor)
__global__ __launch_bounds__(256)
void transpose_w64_dual_kernel(const float* __restrict__ in0, __half* __restrict__ out0,
                               const float* __restrict__ in1, __half* __restrict__ out1)
{
    __shared__ float tile[32][33];
    const float* in = blockIdx.z ? in1 : in0;
    __half* out = blockIdx.z ? out1 : out0;
    const int tx = threadIdx.x & 31;
    const int ty = threadIdx.x >> 5;       // 0..7
    const int x0 = blockIdx.x * 32;
    const int y0 = blockIdx.y * 32;
#pragma unroll
    for (int i = 0; i < 32; i += 8)
        tile[ty + i][tx] = in[(size_t)(y0 + ty + i) * Dq + x0 + tx];
    __syncthreads();
#pragma unroll
    for (int i = 0; i < 32; i += 8)
        out[(size_t)(x0 + ty + i) * Dq + y0 + tx] = __float2half_rn(tile[tx][ty + i] * 64.0f);
}

// out[i] = sum_k W[i,k]*v[k] + b2[i], dual (blockIdx.y selects problem)
__global__ __launch_bounds__(256)
void matvec_bias_dual_kernel(const float* __restrict__ W0, const float* __restrict__ v0,
                             const float* __restrict__ b20, float* __restrict__ out0,
                             const float* __restrict__ W1, const float* __restrict__ v1,
                             const float* __restrict__ b21, float* __restrict__ out1)
{
    const float* W = blockIdx.y ? W1 : W0;
    const float* v = blockIdx.y ? v1 : v0;
    const float* b2 = blockIdx.y ? b21 : b20;
    float* out = blockIdx.y ? out1 : out0;
    const int row  = blockIdx.x * 8 + (threadIdx.x >> 5);
    const int lane = threadIdx.x & 31;
    const float* r = W + (size_t)row * Dq;
    float s = 0.0f;
#pragma unroll
    for (int k = lane * 4; k < Dq; k += 128) {
        float4 a = *(const float4*)(r + k);
        float4 x = *(const float4*)(v + k);
        s += a.x * x.x + a.y * x.y + a.z * x.z + a.w * x.w;
    }
#pragma unroll
    for (int o = 16; o > 0; o >>= 1) s += __shfl_xor_sync(0xFFFFFFFFu, s, o);
    if (lane == 0) out[row] = s + b2[row];
}

// ---------------------------------------------------------------------------
// fp16 single-product GEMM body (NT): C = (A * W64) / 64 + bias (+resid)
// CTA tile 128x128, K-step 32, 4-stage cp.async, 8 warps, 2 CTAs/SM.
// bm/bn passed explicitly so multiple logical GEMMs can share one launch.
// ---------------------------------------------------------------------------
constexpr int TILE_B   = 10240;             // 128 rows * 80 B
constexpr int STAGE_B  = 2 * TILE_B;        // A | W
constexpr int SMEM_TOT = 4 * STAGE_B;       // 81920

__device__ __forceinline__ void load_stage(
    uint32_t sb_stage, int kb, int tid,
    const __half* __restrict__ A, const __half* __restrict__ W, int bm, int bn)
{
    const __half* srcs[2] = {A, W};
    const int rb[2] = {bm, bn};
#pragma unroll
    for (int t = 0; t < 2; t++) {
#pragma unroll
        for (int i = 0; i < 2; i++) {
            const int idx = i * 256 + tid;     // 0..511
            const int row = idx >> 2;
            const int ch  = idx & 3;
            const __half* g = srcs[t] + (((size_t)(rb[t] + row)) << 10) + kb * 32 + ch * 8;
            const uint32_t d = sb_stage + t * TILE_B + row * 80 + ch * 16;
            CP_ASYNC16(d, g);
        }
    }
}

template <bool OUT_FP16, bool RESID>
__device__ __forceinline__ void gemm_body(
    const __half* __restrict__ A, const __half* __restrict__ W,
    const float* __restrict__ bias, const float* __restrict__ resid,
    float* __restrict__ Cf, __half* __restrict__ Ch, int bm, int bn)
{
    extern __shared__ __align__(128) char smem[];
    const uint32_t sb = smem_u32(smem);
    const int tid  = threadIdx.x;
    const int wid  = tid >> 5;
    const int lane = tid & 31;
    const int wm = (wid >> 1) * 32;
    const int wn = (wid & 1) * 64;

    float acc[2][8][4];
#pragma unroll
    for (int i = 0; i < 2; i++)
#pragma unroll
        for (int j = 0; j < 8; j++)
#pragma unroll
            for (int k = 0; k < 4; k++) acc[i][j][k] = 0.0f;

    load_stage(sb + 0 * STAGE_B, 0, tid, A, W, bm, bn); CP_COMMIT();
    load_stage(sb + 1 * STAGE_B, 1, tid, A, W, bm, bn); CP_COMMIT();
    load_stage(sb + 2 * STAGE_B, 2, tid, A, W, bm, bn); CP_COMMIT();

    const int sub = lane >> 3;
    const int rr  = lane & 7;

    for (int kb = 0; kb < 32; kb++) {
        CP_WAIT2();
        __syncthreads();
        if (kb + 3 < 32)
            load_stage(sb + ((kb + 3) & 3) * STAGE_B, kb + 3, tid, A, W, bm, bn);
        CP_COMMIT();

        const uint32_t st = sb + (kb & 3) * STAGE_B;
        const uint32_t sA = st;
        const uint32_t sB = st + TILE_B;

#pragma unroll
        for (int kk = 0; kk < 2; kk++) {
            const int chunk = kk * 2 + (sub >> 1);
            uint32_t fa[2][4], fb[4][4];
#pragma unroll
            for (int mt = 0; mt < 2; mt++) {
                const int row = wm + mt * 16 + (sub & 1) * 8 + rr;
                ldsm4(fa[mt], sA + row * 80 + chunk * 16);
            }
#pragma unroll
            for (int g = 0; g < 4; g++) {
                const int row = wn + g * 16 + (sub & 1) * 8 + rr;
                ldsm4(fb[g], sB + row * 80 + chunk * 16);
            }
#pragma unroll
            for (int mt = 0; mt < 2; mt++) {
#pragma unroll
                for (int g = 0; g < 4; g++) {
                    mma_f16(acc[mt][2 * g],     fa[mt], fb[g][0], fb[g][2]);
                    mma_f16(acc[mt][2 * g + 1], fa[mt], fb[g][1], fb[g][3]);
                }
            }
        }
    }

    const int qrow = lane >> 2;
    const int qcol = (lane & 3) * 2;
#pragma unroll
    for (int mt = 0; mt < 2; mt++) {
#pragma unroll
        for (int nt = 0; nt < 8; nt++) {
            const int col = bn + wn + nt * 8 + qcol;
            const float bz0 = __ldg(bias + col - bn + (bn ? 0 : 0) + 0) * 0.0f + __ldg(bias + col);
            const float bz1 = __ldg(bias + col + 1);
#pragma unroll
            for (int h = 0; h < 2; h++) {
                const int row = bm + wm + mt * 16 + h * 8 + qrow;
                float v0 = acc[mt][nt][2 * h + 0] * 0.015625f + bz0;
                float v1 = acc[mt][nt][2 * h + 1] * 0.015625f + bz1;
                const size_t go = ((size_t)row << 10) + col;
                if (RESID) {
                    float2 x2 = *(const float2*)(resid + go);
                    v0 += x2.x; v1 += x2.y;
                }
                if (OUT_FP16) {
                    __half2 hv = __floats2half2_rn(v0, v1);
                    *(uint32_t*)(Ch + go) = *(uint32_t*)&hv;
                } else {
                    float2 o; o.x = v0; o.y = v1;
                    *(float2*)(Cf + go) = o;
                }
            }
        }
    }
}

// value GEMM (1024 tiles) + the two weight-combine GEMMs (128 tiles), packed
// into one launch: grid (8, 144).
__global__ __launch_bounds__(256, 2)
void gemm_value_combine(
    const __half* __restrict__ xh, const __half* __restrict__ whV,
    const float* __restrict__ bv, __half* __restrict__ vh,
    const __half* __restrict__ whKP, const __half* __restrict__ whKT, __half* __restrict__ whCK,
    const __half* __restrict__ whQP, const __half* __restrict__ whQT, __half* __restrict__ whCQ,
    const float* __restrict__ zerob)
{
    const int by = blockIdx.y;
    const int bn = blockIdx.x * 128;
    if (by < 128) {
        gemm_body<true, false>(xh, whV, bv, nullptr, nullptr, vh, by * 128, bn);
    } else if (by < 136) {
        gemm_body<true, false>(whKP, whKT, zerob, nullptr, nullptr, whCK, (by - 128) * 128, bn);
    } else {
        gemm_body<true, false>(whQP, whQT, zerob, nullptr, nullptr, whCQ, (by - 136) * 128, bn);
    }
}

// kp + qp GEMMs in one launch: grid (8, 128, 2)
__global__ __launch_bounds__(256, 2)
void gemm_kq_dual(const __half* __restrict__ xh,
                  const __half* __restrict__ whCK, const float* __restrict__ bkpc, __half* __restrict__ kh,
                  const __half* __restrict__ whCQ, const float* __restrict__ bqpc, __half* __restrict__ qh)
{
    if (blockIdx.z == 0)
        gemm_body<true, false>(xh, whCK, bkpc, nullptr, nullptr, kh, blockIdx.y * 128, blockIdx.x * 128);
    else
        gemm_body<true, false>(xh, whCQ, bqpc, nullptr, nullptr, qh, blockIdx.y * 128, blockIdx.x * 128);
}

// out-projection GEMM with residual, fp32 output
__global__ __launch_bounds__(256, 2)
void gemm_out(const __half* __restrict__ A, const __half* __restrict__ W,
              const float* __restrict__ bias, const float* __restrict__ resid,
              float* __restrict__ Cf)
{
    gemm_body<false, true>(A, W, bias, resid, Cf, nullptr, blockIdx.y * 128, blockIdx.x * 128);
}

// ---------------------------------------------------------------------------
// Fused phasor + LayerNorm: one block per chunk (64 s-rows x 1024 d).
// 256 threads x 4 d. 4 s-steps share one block-reduction round (2 syncs / 4 rows).
// ---------------------------------------------------------------------------
__global__ __launch_bounds__(256)
void lnphasor_kernel(const __half* __restrict__ kp16, const __half* __restrict__ qp16,
                     const __half* __restrict__ v16,  const float* __restrict__ ps,
                     const float* __restrict__ lng,   const float* __restrict__ lnb,
                     __half* __restrict__ outh)
{
    __shared__ float sred[64];   // [8 values][8 warps]
    __shared__ float smu[8];     // s1[0..3], s2[0..3]
    const int tid  = threadIdx.x;
    const int warp = tid >> 5;
    const int lane = tid & 31;
    const int d0 = tid * 4;

    const float4 ps4 = *(const float4*)(ps + d0);
    const float4 g4  = *(const float4*)(lng + d0);
    const float4 b4  = *(const float4*)(lnb + d0);
    const float psv[4] = {ps4.x, ps4.y, ps4.z, ps4.w};
    const float gv[4]  = {g4.x, g4.y, g4.z, g4.w};
    const float bv[4]  = {b4.x, b4.y, b4.z, b4.w};

    float mr[4] = {0, 0, 0, 0}, mi[4] = {0, 0, 0, 0};
    const size_t base = ((size_t)blockIdx.x * CHUNKq << 10) + d0;

    for (int s4 = 0; s4 < CHUNKq / 4; s4++) {
        float r[4][4];
        float s1[4], s2[4];
#pragma unroll
        for (int u = 0; u < 4; u++) {
            const size_t off = base + ((size_t)(s4 * 4 + u) << 10);
            uint2 kpu = *(const uint2*)(kp16 + off);
            uint2 qpu = *(const uint2*)(qp16 + off);
            uint2 vu  = *(const uint2*)(v16 + off);
            float2 kpa = __half22float2(*(__half2*)&kpu.x);
            float2 kpb = __half22float2(*(__half2*)&kpu.y);
            float2 qpa = __half22float2(*(__half2*)&qpu.x);
            float2 qpb = __half22float2(*(__half2*)&qpu.y);
            float2 va  = __half22float2(*(__half2*)&vu.x);
            float2 vb  = __half22float2(*(__half2*)&vu.y);
            const float kpf[4] = {kpa.x, kpa.y, kpb.x, kpb.y};
            const float qpf[4] = {qpa.x, qpa.y, qpb.x, qpb.y};
            const float vf[4]  = {va.x, va.y, vb.x, vb.y};
            float a1 = 0.0f, a2 = 0.0f;
#pragma unroll
            for (int j = 0; j < 4; j++) {
                const float kp = ftanh(kpf[j]) * psv[j];
                const float qp = ftanh(qpf[j]) * psv[j];
                mr[j] = fmaf(vf[j], fcos(kp), mr[j]);
                mi[j] = fmaf(vf[j], fsin(kp), mi[j]);
                r[u][j] = (mr[j] * fcos(qp) + mi[j] * fsin(qp)) * 0.03125f;
                a1 += r[u][j];
                a2 = fmaf(r[u][j], r[u][j], a2);
            }
            s1[u] = a1; s2[u] = a2;
        }
        // warp reduce all 8 partials
#pragma unroll
        for (int o = 16; o > 0; o >>= 1) {
#pragma unroll
            for (int u = 0; u < 4; u++) {
                s1[u] += __shfl_xor_sync(0xFFFFFFFFu, s1[u], o);
                s2[u] += __shfl_xor_sync(0xFFFFFFFFu, s2[u], o);
            }
        }
        if (lane == 0) {
#pragma unroll
            for (int u = 0; u < 4; u++) {
                sred[u * 8 + warp] = s1[u];
                sred[(4 + u) * 8 + warp] = s2[u];
            }
        }
        __syncthreads();
        if (warp == 0) {
            float a = sred[lane];        // entries 0..31: v = lane>>3 (s1[0..3])
            float b = sred[lane + 32];   // entries 32..63: v = 4 + (lane>>3) (s2)
#pragma unroll
            for (int o = 4; o > 0; o >>= 1) {
                a += __shfl_xor_sync(0xFFFFFFFFu, a, o);
                b += __shfl_xor_sync(0xFFFFFFFFu, b, o);
            }
            if ((lane & 7) == 0) {
                smu[lane >> 3] = a;
                smu[4 + (lane >> 3)] = b;
            }
        }
        __syncthreads();
#pragma unroll
        for (int u = 0; u < 4; u++) {
            const float mu   = smu[u] * (1.0f / Dq);
            const float var  = smu[4 + u] * (1.0f / Dq) - mu * mu;
            const float rstd = rsqrtf(var + 1e-5f);
            __half2 h0 = __floats2half2_rn((r[u][0] - mu) * rstd * gv[0] + bv[0],
                                           (r[u][1] - mu) * rstd * gv[1] + bv[1]);
            __half2 h1 = __floats2half2_rn((r[u][2] - mu) * rstd * gv[2] + bv[2],
                                           (r[u][3] - mu) * rstd * gv[3] + bv[3]);
            uint2 p;
            p.x = *(uint32_t*)&h0;
            p.y = *(uint32_t*)&h1;
            const size_t off = base + ((size_t)(s4 * 4 + u) << 10);
            *(uint2*)(outh + off) = p;
        }
        __syncthreads();   // protect smu/sred before next batch overwrites
    }
}

// ---------------------------------------------------------------------------
// Launch
// ---------------------------------------------------------------------------
extern "C" void kernel_launch(void* const* d_in, const int* in_sizes, int n_in,
                              void* d_out, int out_size)
{
    (void)in_sizes; (void)n_in; (void)out_size;
    const float* x   = (const float*)d_in[0];
    const float* Wk  = (const float*)d_in[1];
    const float* bk  = (const float*)d_in[2];
    const float* Wv  = (const float*)d_in[3];
    const float* bv  = (const float*)d_in[4];
    const float* Wq  = (const float*)d_in[5];
    const float* bq  = (const float*)d_in[6];
    const float* Wkp = (const float*)d_in[7];
    const float* bkp = (const float*)d_in[8];
    const float* Wqp = (const float*)d_in[9];
    const float* bqp = (const float*)d_in[10];
    const float* ps  = (const float*)d_in[11];
    const float* lng = (const float*)d_in[12];
    const float* lnb = (const float*)d_in[13];
    const float* Wo  = (const float*)d_in[14];
    const float* bo  = (const float*)d_in[15];
    float* out = (float*)d_out;

    float *zero, *bkpc, *bqpc;
    __half *xh, *vh, *kh, *qh, *ah, *wh;
    cudaGetSymbolAddress((void**)&xh, g_xh);
    cudaGetSymbolAddress((void**)&vh, g_vh);
    cudaGetSymbolAddress((void**)&kh, g_kh);
    cudaGetSymbolAddress((void**)&qh, g_qh);
    cudaGetSymbolAddress((void**)&ah, g_ah);
    cudaGetSymbolAddress((void**)&wh, g_wh);
    cudaGetSymbolAddress((void**)&zero, g_zero);
    cudaGetSymbolAddress((void**)&bkpc, g_bkp);
    cudaGetSymbolAddress((void**)&bqpc, g_bqp);

    cudaFuncSetAttribute(gemm_value_combine, cudaFuncAttributeMaxDynamicSharedMemorySize, SMEM_TOT);
    cudaFuncSetAttribute(gemm_kq_dual,       cudaFuncAttributeMaxDynamicSharedMemorySize, SMEM_TOT);
    cudaFuncSetAttribute(gemm_out,           cudaFuncAttributeMaxDynamicSharedMemorySize, SMEM_TOT);

    const size_t WN = (size_t)Dq * Dq;
    __half* whV  = wh + 0 * WN;
    __half* whO  = wh + 1 * WN;
    __half* whKP = wh + 2 * WN;
    __half* whQP = wh + 3 * WN;
    __half* whKT = wh + 4 * WN;
    __half* whQT = wh + 5 * WN;
    __half* whCK = wh + 6 * WN;
    __half* whCQ = wh + 7 * WN;

    // Prep (merged launches)
    convert_kernel<<<(Mq * Dq) / 1024, 256>>>(x, xh);
    convert_w64_quad_kernel<<<dim3(WN / 1024, 4), 256>>>(Wv, Wo, Wkp, Wqp, whV, whO, whKP, whQP);
    transpose_w64_dual_kernel<<<dim3(32, 32, 2), 256>>>(Wk, whKT, Wq, whQT);
    matvec_bias_dual_kernel<<<dim3(Dq / 8, 2), 256>>>(Wkp, bk, bkp, bkpc, Wqp, bq, bqp, bqpc);

    const dim3 block(256);
    // value GEMM + weight combines, one launch (1152 CTAs, same wave count as value alone)
    gemm_value_combine<<<dim3(8, 144), block, SMEM_TOT>>>(
        xh, whV, bv, vh, whKP, whKT, whCK, whQP, whQT, whCQ, zero);

    // kp + qp GEMMs, one launch (2048 CTAs = 7 waves vs 8 separate)
    gemm_kq_dual<<<dim3(8, 128, 2), block, SMEM_TOT>>>(xh, whCK, bkpc, kh, whCQ, bqpc, qh);

    // Fused phasor + layernorm -> ah (fp16)
    lnphasor_kernel<<<Bq * NCHUNK, 256>>>(kh, qh, vh, ps, lng, lnb, ah);

    // out = x + ln @ Wo + bo
    gemm_out<<<dim3(8, 128), block, SMEM_TOT>>>(ah, whO, bo, x, out);
}